// round 4
// baseline (speedup 1.0000x reference)
#include <cuda_runtime.h>
#include <cuda_bf16.h>
#include <cstdint>
#include <math.h>

// Problem constants
#define NROWS 1024
#define DDIM  512
#define NCLS  70722
#define NT    553            // ceil(NCLS/128)
#define CPAD  (NT*128)       // 70784
#define PADC  (CPAD - NCLS)  // 62 zero padding classes (logit exactly 0)
#define M_MARGIN 0.4f
#define H_SCALE  0.333f
#define S_SCALE  64.0f
#define EPS_M    0.001f
#define PI_F     3.14159265358979f
#define COS_CLIP 0.99999950f   // cos(0.001)

// GEMM tiling (int8, IMMA m16n8k32)
#define BM 128
#define BN 128
#define BK 64                 // int8 elements (=bytes) per k-tile
#define PAD 16                // byte pad per smem row (stride 80B, 16B-aligned)
#define NKT (DDIM/BK)         // 8

// ---------------- device scratch (static: no allocations) ----------------
__device__ int8_t g_A[NROWS*DDIM];               // quantized normalized x
__device__ int8_t g_W[(size_t)CPAD*DDIM];        // quantized normalized weights (~36MB)
__device__ float g_sa[NROWS];                    // per-row dequant scale for A
__device__ float g_sw[CPAD];                     // per-class dequant scale for W (0 on pad)
__device__ float g_xnorm[NROWS];
__device__ float g_gang[NROWS];
__device__ float g_gadd[NROWS];
__device__ float g_pmax[(size_t)NROWS*NT];
__device__ float g_psum[(size_t)NROWS*NT];
__device__ float g_lab_plain[NROWS];
__device__ float g_lab_adj[NROWS];
__device__ float g_loss[NROWS];

// ---------------- helpers ----------------
__device__ __forceinline__ float warpReduceSum(float v) {
#pragma unroll
    for (int o = 16; o > 0; o >>= 1) v += __shfl_xor_sync(0xffffffffu, v, o);
    return v;
}
__device__ __forceinline__ float warpReduceMax(float v) {
#pragma unroll
    for (int o = 16; o > 0; o >>= 1) v = fmaxf(v, __shfl_xor_sync(0xffffffffu, v, o));
    return v;
}
__device__ __forceinline__ uint32_t smem_u32(const void* p) {
    return (uint32_t)__cvta_generic_to_shared(p);
}
__device__ __forceinline__ void cp16(uint32_t s, const void* g) {
    asm volatile("cp.async.cg.shared.global [%0], [%1], 16;\n" :: "r"(s), "l"(g));
}
__device__ __forceinline__ void lse_combine(float& m, float& s, float om, float os) {
    float nm = fmaxf(m, om);
    s = s * __expf(m - nm) + os * __expf(om - nm);
    m = nm;
}
__device__ __forceinline__ int q8(float v) {
    int q = __float2int_rn(v);
    return max(-127, min(127, q));
}

// ---------------- prep kernels ----------------
__global__ void prep_x_kernel(const float* __restrict__ x) {
    int row = blockIdx.x, tid = threadIdx.x;          // 128 threads
    const float4* xr = (const float4*)(x + (size_t)row * DDIM);
    float4 v = xr[tid];
    float ss = v.x*v.x + v.y*v.y + v.z*v.z + v.w*v.w;
    float mx = fmaxf(fmaxf(fabsf(v.x), fabsf(v.y)), fmaxf(fabsf(v.z), fabsf(v.w)));
    __shared__ float rs[4], rmx[4];
    ss = warpReduceSum(ss);
    mx = warpReduceMax(mx);
    if ((tid & 31) == 0) { rs[tid >> 5] = ss; rmx[tid >> 5] = mx; }
    __syncthreads();
    float tot = rs[0] + rs[1] + rs[2] + rs[3];
    float mv  = fmaxf(fmaxf(rmx[0], rmx[1]), fmaxf(rmx[2], rmx[3]));
    float nrm = sqrtf(tot);
    if (tid == 0) {
        g_xnorm[row] = nrm;
        g_sa[row] = mv / (127.0f * fmaxf(nrm, 1e-12f));
    }
    float qs = 127.0f / mv;
    int q0 = q8(v.x*qs), q1 = q8(v.y*qs), q2 = q8(v.z*qs), q3 = q8(v.w*qs);
    uint32_t pk = (q0 & 0xff) | ((q1 & 0xff) << 8) | ((q2 & 0xff) << 16) | ((q3 & 0xff) << 24);
    ((uint32_t*)g_A)[(size_t)row * (DDIM/4) + tid] = pk;
}

__global__ void prep_w_kernel(const float* __restrict__ w) {
    int row = blockIdx.x, tid = threadIdx.x;          // 128 threads, CPAD blocks
    uint32_t pk = 0u;
    if (row < NCLS) {
        const float4* wr = (const float4*)(w + (size_t)row * DDIM);
        float4 v = wr[tid];
        float ss = v.x*v.x + v.y*v.y + v.z*v.z + v.w*v.w;
        float mx = fmaxf(fmaxf(fabsf(v.x), fabsf(v.y)), fmaxf(fabsf(v.z), fabsf(v.w)));
        __shared__ float rs[4], rmx[4];
        ss = warpReduceSum(ss);
        mx = warpReduceMax(mx);
        if ((tid & 31) == 0) { rs[tid >> 5] = ss; rmx[tid >> 5] = mx; }
        __syncthreads();
        float tot = rs[0] + rs[1] + rs[2] + rs[3];
        float mv  = fmaxf(fmaxf(rmx[0], rmx[1]), fmaxf(rmx[2], rmx[3]));
        if (tid == 0) g_sw[row] = mv / (127.0f * fmaxf(sqrtf(tot), 1e-12f));
        float qs = 127.0f / mv;
        int q0 = q8(v.x*qs), q1 = q8(v.y*qs), q2 = q8(v.z*qs), q3 = q8(v.w*qs);
        pk = (q0 & 0xff) | ((q1 & 0xff) << 8) | ((q2 & 0xff) << 16) | ((q3 & 0xff) << 24);
    } else {
        if (tid == 0) g_sw[row] = 0.0f;
    }
    ((uint32_t*)g_W)[(size_t)row * (DDIM/4) + tid] = pk;
}

__global__ void stats_kernel() {
    int tid = threadIdx.x;                            // 1024 threads
    float n = g_xnorm[tid];
    float s = fminf(fmaxf(fmaxf(n, 1e-8f), 0.001f), 100.0f);
    __shared__ float red[32];
    float t = warpReduceSum(s);
    if ((tid & 31) == 0) red[tid >> 5] = t;
    __syncthreads();
    if (tid < 32) { float v = red[tid]; v = warpReduceSum(v); if (tid == 0) red[0] = v; }
    __syncthreads();
    float mean = red[0] / (float)NROWS;
    float d = s - mean;
    __syncthreads();
    t = warpReduceSum(d * d);
    if ((tid & 31) == 0) red[tid >> 5] = t;
    __syncthreads();
    if (tid < 32) { float v = red[tid]; v = warpReduceSum(v); if (tid == 0) red[0] = v; }
    __syncthreads();
    float stdv = sqrtf(red[0] / (float)(NROWS - 1));   // ddof=1
    float ms = fminf(fmaxf(d / (stdv + EPS_M) * H_SCALE, -1.0f), 1.0f);
    g_gang[tid] = -M_MARGIN * ms;
    g_gadd[tid] = M_MARGIN + M_MARGIN * ms;
}

__global__ void label_kernel(const float* __restrict__ x,
                             const int* __restrict__ labels,
                             const float* __restrict__ w) {
    int i = blockIdx.x, tid = threadIdx.x;            // 128 threads
    int l = labels[i];
    l = max(0, min(l, NCLS - 1));                     // safety clamp
    const float4* xr = (const float4*)(x + (size_t)i * DDIM);
    const float4* wr = (const float4*)(w + (size_t)l * DDIM);
    float4 a = xr[tid], b = wr[tid];
    float dot = a.x*b.x + a.y*b.y + a.z*b.z + a.w*b.w;
    float wsq = b.x*b.x + b.y*b.y + b.z*b.z + b.w*b.w;
    __shared__ float rd[4], rw[4];
    dot = warpReduceSum(dot);
    wsq = warpReduceSum(wsq);
    if ((tid & 31) == 0) { rd[tid >> 5] = dot; rw[tid >> 5] = wsq; }
    __syncthreads();
    if (tid == 0) {
        float Dv = rd[0] + rd[1] + rd[2] + rd[3];
        float Wv = rw[0] + rw[1] + rw[2] + rw[3];
        float xn = fmaxf(g_xnorm[i], 1e-12f);
        float wn = fmaxf(sqrtf(Wv), 1e-12f);
        float c  = fminf(fmaxf(Dv / (xn * wn), -1.0f), 1.0f);
        float th = acosf(c);
        float plain = S_SCALE * cosf(fminf(fmaxf(th, EPS_M), PI_F - EPS_M));
        float thm = fminf(fmaxf(th + g_gang[i], EPS_M), PI_F - EPS_M);
        float adj = S_SCALE * (cosf(thm) - g_gadd[i]);
        g_lab_plain[i] = plain;
        g_lab_adj[i]   = adj;
    }
}

// ---------------- main fused int8 GEMM + online LSE ----------------
__global__ void __launch_bounds__(256, 2) gemm_lse_kernel() {
    // grid: (8 m-tiles, 553 c-tiles); x fast so concurrent CTAs share B tiles in L2
    int mt = blockIdx.x, ct = blockIdx.y;
    int tid = threadIdx.x;
    int lane = tid & 31, warp = tid >> 5;
    int wm = warp & 3;        // 0..3 -> m offset
    int wn = warp >> 2;       // 0..1 -> n offset

    __shared__ __align__(16) int8_t sA[2][BM][BK + PAD];
    __shared__ __align__(16) int8_t sB[2][BN][BK + PAD];
    __shared__ float sMax[2][BM];
    __shared__ float sSum[2][BM];
    __shared__ float sSa[BM];
    __shared__ float sSw[BN];

    const int m0 = mt * BM;
    const int n0 = ct * BN;

    if (tid < BM) {
        sSa[tid] = g_sa[m0 + tid];
        sSw[tid] = g_sw[n0 + tid];
    }

    int acc[2][8][4];
#pragma unroll
    for (int i = 0; i < 2; i++)
#pragma unroll
        for (int j = 0; j < 8; j++)
#pragma unroll
            for (int k = 0; k < 4; k++) acc[i][j][k] = 0;

    // loaders: each thread moves 2x16B for A and 2x16B for B per K-tile
    int ar = tid >> 2;            // 0..63
    int ac = (tid & 3) * 16;      // 0,16,32,48 (bytes)
    const int8_t* gA = g_A + (size_t)(m0 + ar) * DDIM + ac;
    const int8_t* gB = g_W + (size_t)(n0 + ar) * DDIM + ac;

#define LOAD_TILE(buf, kt) do {                                             \
        int _k0 = (kt) * BK;                                                \
        cp16(smem_u32(&sA[buf][ar     ][ac]), gA + _k0);                    \
        cp16(smem_u32(&sA[buf][ar + 64][ac]), gA + (size_t)64*DDIM + _k0);  \
        cp16(smem_u32(&sB[buf][ar     ][ac]), gB + _k0);                    \
        cp16(smem_u32(&sB[buf][ar + 64][ac]), gB + (size_t)64*DDIM + _k0);  \
        asm volatile("cp.async.commit_group;\n" ::);                        \
    } while (0)

    LOAD_TILE(0, 0);

    for (int kt = 0; kt < NKT; kt++) {
        if (kt + 1 < NKT) LOAD_TILE((kt + 1) & 1, kt + 1);
        else asm volatile("cp.async.commit_group;\n" ::);   // empty group so wait 1 == tile done
        asm volatile("cp.async.wait_group 1;\n" ::: "memory");
        __syncthreads();

        int buf = kt & 1;
#pragma unroll
        for (int kk = 0; kk < 2; kk++) {
            int kb = kk * 32 + (lane >> 4) * 16;            // byte offset in row
            uint32_t a_r[2][4];
#pragma unroll
            for (int mi = 0; mi < 2; mi++) {
                uint32_t addr = smem_u32(&sA[buf][wm*32 + mi*16 + (lane & 15)][kb]);
                asm volatile("ldmatrix.sync.aligned.m8n8.x4.shared.b16 {%0,%1,%2,%3}, [%4];"
                             : "=r"(a_r[mi][0]), "=r"(a_r[mi][1]), "=r"(a_r[mi][2]), "=r"(a_r[mi][3])
                             : "r"(addr));
            }
            uint32_t b_r[8][2];
#pragma unroll
            for (int nj = 0; nj < 4; nj++) {
                uint32_t addr = smem_u32(&sB[buf][wn*64 + nj*16 + (lane & 15)][kb]);
                uint32_t r0, r1, r2, r3;
                asm volatile("ldmatrix.sync.aligned.m8n8.x4.shared.b16 {%0,%1,%2,%3}, [%4];"
                             : "=r"(r0), "=r"(r1), "=r"(r2), "=r"(r3)
                             : "r"(addr));
                b_r[2*nj][0] = r0; b_r[2*nj+1][0] = r1;
                b_r[2*nj][1] = r2; b_r[2*nj+1][1] = r3;
            }
#pragma unroll
            for (int mi = 0; mi < 2; mi++)
#pragma unroll
                for (int ni = 0; ni < 8; ni++) {
                    asm volatile(
                        "mma.sync.aligned.m16n8k32.row.col.s32.s8.s8.s32 "
                        "{%0,%1,%2,%3}, {%4,%5,%6,%7}, {%8,%9}, {%0,%1,%2,%3};"
                        : "+r"(acc[mi][ni][0]), "+r"(acc[mi][ni][1]),
                          "+r"(acc[mi][ni][2]), "+r"(acc[mi][ni][3])
                        : "r"(a_r[mi][0]), "r"(a_r[mi][1]), "r"(a_r[mi][2]), "r"(a_r[mi][3]),
                          "r"(b_r[ni][0]), "r"(b_r[ni][1]));
                }
        }
        __syncthreads();
    }
#undef LOAD_TILE

    // ---- epilogue: dequant -> clamp -> logits -> per-row online (max, sumexp) ----
#pragma unroll
    for (int mi = 0; mi < 2; mi++) {
#pragma unroll
        for (int half = 0; half < 2; half++) {
            int rw = wm*32 + mi*16 + half*8 + (lane >> 2);     // row within CTA
            float sa = sSa[rw];
            float mx = -1e30f;
            float lg[8][2];
#pragma unroll
            for (int ni = 0; ni < 8; ni++)
#pragma unroll
                for (int e = 0; e < 2; e++) {
                    int cc = wn*64 + ni*8 + (lane & 3)*2 + e;
                    float cosv = __int2float_rn(acc[mi][ni][half*2 + e]) * sa * sSw[cc];
                    float v = S_SCALE * fminf(fmaxf(cosv, -COS_CLIP), COS_CLIP);
                    lg[ni][e] = v;
                    mx = fmaxf(mx, v);
                }
            float sm = 0.0f;
#pragma unroll
            for (int ni = 0; ni < 8; ni++)
#pragma unroll
                for (int e = 0; e < 2; e++)
                    sm += __expf(lg[ni][e] - mx);
            // reduce across the 4 lanes of the quad (they share the same row)
#pragma unroll
            for (int o = 1; o < 4; o <<= 1) {
                float om = __shfl_xor_sync(0xffffffffu, mx, o);
                float os = __shfl_xor_sync(0xffffffffu, sm, o);
                lse_combine(mx, sm, om, os);
            }
            if ((lane & 3) == 0) { sMax[wn][rw] = mx; sSum[wn][rw] = sm; }
        }
    }
    __syncthreads();

    if (tid < BM) {
        float m = sMax[0][tid], s = sSum[0][tid];
        lse_combine(m, s, sMax[1][tid], sSum[1][tid]);
        int grow = m0 + tid;
        g_pmax[(size_t)grow * NT + ct] = m;
        g_psum[(size_t)grow * NT + ct] = s;
    }
}

// ---------------- final reductions ----------------
__global__ void reduce1_kernel() {
    int row = blockIdx.x, tid = threadIdx.x;   // 128 threads
    float mx = -1e30f, sm = 0.0f;
    for (int t = tid; t < NT; t += 128) {
        float m = g_pmax[(size_t)row * NT + t];
        float s = g_psum[(size_t)row * NT + t];
        lse_combine(mx, sm, m, s);
    }
#pragma unroll
    for (int o = 16; o > 0; o >>= 1) {
        float om = __shfl_xor_sync(0xffffffffu, mx, o);
        float os = __shfl_xor_sync(0xffffffffu, sm, o);
        lse_combine(mx, sm, om, os);
    }
    __shared__ float rm[4], rs[4];
    int lane = tid & 31, w = tid >> 5;
    if (lane == 0) { rm[w] = mx; rs[w] = sm; }
    __syncthreads();
    if (tid == 0) {
        float m = rm[0], s = rs[0];
        lse_combine(m, s, rm[1], rs[1]);
        lse_combine(m, s, rm[2], rs[2]);
        lse_combine(m, s, rm[3], rs[3]);
        // remove PADC padding terms (logit exactly 0), swap plain->adjusted label term
        float plain = g_lab_plain[row], adj = g_lab_adj[row];
        float s2 = s - (float)PADC * __expf(0.0f - m) - __expf(plain - m) + __expf(adj - m);
        float lse = m + __logf(s2);
        g_loss[row] = lse - adj;
    }
}

__global__ void reduce2_kernel(float* __restrict__ out) {
    int tid = threadIdx.x;    // 256 threads
    float s = 0.0f;
    for (int t = tid; t < NROWS; t += 256) s += g_loss[t];
    s = warpReduceSum(s);
    __shared__ float red[8];
    if ((tid & 31) == 0) red[tid >> 5] = s;
    __syncthreads();
    if (tid == 0) {
        float tot = 0.0f;
        for (int i = 0; i < 8; i++) tot += red[i];
        out[0] = tot / (float)NROWS;
    }
}

// ---------------- launch ----------------
extern "C" void kernel_launch(void* const* d_in, const int* in_sizes, int n_in,
                              void* d_out, int out_size) {
    const float* x      = (const float*)d_in[0];
    const int*   labels = (const int*)d_in[1];
    const float* w      = (const float*)d_in[2];
    float* out = (float*)d_out;

    // order chosen so the GEMM sits at the ncu capture slot
    prep_x_kernel<<<NROWS, 128>>>(x);
    prep_w_kernel<<<CPAD, 128>>>(w);
    stats_kernel<<<1, 1024>>>();
    gemm_lse_kernel<<<dim3(8, NT), 256>>>();
    label_kernel<<<NROWS, 128>>>(x, labels, w);
    reduce1_kernel<<<NROWS, 128>>>();
    reduce2_kernel<<<1, 256>>>(out);
}

// round 5
// speedup vs baseline: 1.7335x; 1.7335x over previous
#include <cuda_runtime.h>
#include <cuda_fp16.h>
#include <cstdint>
#include <math.h>

// Problem constants
#define NROWS 1024
#define DDIM  512
#define NCLS  70722
#define NT    553            // ceil(NCLS/128)
#define CPAD  (NT*128)       // 70784
#define PADC  (CPAD - NCLS)  // 62 zero padding classes (logit exactly 0)
#define M_MARGIN 0.4f
#define H_SCALE  0.333f
#define S_SCALE  64.0f
#define EPS_M    0.001f
#define PI_F     3.14159265358979f
#define COS_CLIP 0.99999950f   // cos(0.001)

// GEMM tiling (f16, HMMA m16n8k16, f16 accumulate)
#define BM 128
#define BN 128
#define BK 32                 // f16 elements per k-tile
#define PAD 8
#define NKT (DDIM/BK)         // 16

// ---------------- device scratch (static: no allocations) ----------------
__device__ __half g_A[NROWS*DDIM];               // normalized x, f16
__device__ __half g_W[(size_t)CPAD*DDIM];        // normalized weights, f16 (~72.5MB)
__device__ float g_xnorm[NROWS];
__device__ float g_gang[NROWS];
__device__ float g_gadd[NROWS];
__device__ float g_pmax[(size_t)NROWS*NT];
__device__ float g_psum[(size_t)NROWS*NT];
__device__ float g_lab_plain[NROWS];
__device__ float g_lab_adj[NROWS];
__device__ float g_loss[NROWS];

// ---------------- helpers ----------------
__device__ __forceinline__ float warpReduceSum(float v) {
#pragma unroll
    for (int o = 16; o > 0; o >>= 1) v += __shfl_xor_sync(0xffffffffu, v, o);
    return v;
}
__device__ __forceinline__ uint32_t smem_u32(const void* p) {
    return (uint32_t)__cvta_generic_to_shared(p);
}
__device__ __forceinline__ void cp16(uint32_t s, const void* g) {
    asm volatile("cp.async.cg.shared.global [%0], [%1], 16;\n" :: "r"(s), "l"(g));
}
__device__ __forceinline__ void lse_combine(float& m, float& s, float om, float os) {
    float nm = fmaxf(m, om);
    s = s * __expf(m - nm) + os * __expf(om - nm);
    m = nm;
}

// ---------------- prep kernels ----------------
__global__ void prep_x_kernel(const float* __restrict__ x) {
    int row = blockIdx.x, tid = threadIdx.x;          // 128 threads
    const float4* xr = (const float4*)(x + (size_t)row * DDIM);
    float4 v = xr[tid];
    float s = v.x*v.x + v.y*v.y + v.z*v.z + v.w*v.w;
    __shared__ float red[4];
    s = warpReduceSum(s);
    if ((tid & 31) == 0) red[tid >> 5] = s;
    __syncthreads();
    float tot = red[0] + red[1] + red[2] + red[3];
    float nrm = sqrtf(tot);
    if (tid == 0) g_xnorm[row] = nrm;
    float inv = 1.0f / fmaxf(nrm, 1e-12f);
    __half2 h0 = __floats2half2_rn(v.x*inv, v.y*inv);
    __half2 h1 = __floats2half2_rn(v.z*inv, v.w*inv);
    uint2 pk; pk.x = *(unsigned*)&h0; pk.y = *(unsigned*)&h1;
    ((uint2*)g_A)[(size_t)row * (DDIM/4) + tid] = pk;
}

__global__ void prep_w_kernel(const float* __restrict__ w) {
    int row = blockIdx.x, tid = threadIdx.x;          // 128 threads, CPAD blocks
    uint2 pk;
    if (row < NCLS) {
        const float4* wr = (const float4*)(w + (size_t)row * DDIM);
        float4 v = wr[tid];
        float s = v.x*v.x + v.y*v.y + v.z*v.z + v.w*v.w;
        __shared__ float red[4];
        s = warpReduceSum(s);
        if ((tid & 31) == 0) red[tid >> 5] = s;
        __syncthreads();
        float tot = red[0] + red[1] + red[2] + red[3];
        float inv = 1.0f / fmaxf(sqrtf(tot), 1e-12f);
        __half2 h0 = __floats2half2_rn(v.x*inv, v.y*inv);
        __half2 h1 = __floats2half2_rn(v.z*inv, v.w*inv);
        pk.x = *(unsigned*)&h0; pk.y = *(unsigned*)&h1;
    } else {
        pk.x = 0u; pk.y = 0u;    // zero rows -> logit exactly 0, corrected in reduce1
    }
    ((uint2*)g_W)[(size_t)row * (DDIM/4) + tid] = pk;
}

__global__ void stats_kernel() {
    int tid = threadIdx.x;                            // 1024 threads
    float n = g_xnorm[tid];
    float s = fminf(fmaxf(fmaxf(n, 1e-8f), 0.001f), 100.0f);
    __shared__ float red[32];
    float t = warpReduceSum(s);
    if ((tid & 31) == 0) red[tid >> 5] = t;
    __syncthreads();
    if (tid < 32) { float v = red[tid]; v = warpReduceSum(v); if (tid == 0) red[0] = v; }
    __syncthreads();
    float mean = red[0] / (float)NROWS;
    float d = s - mean;
    __syncthreads();
    t = warpReduceSum(d * d);
    if ((tid & 31) == 0) red[tid >> 5] = t;
    __syncthreads();
    if (tid < 32) { float v = red[tid]; v = warpReduceSum(v); if (tid == 0) red[0] = v; }
    __syncthreads();
    float stdv = sqrtf(red[0] / (float)(NROWS - 1));   // ddof=1
    float ms = fminf(fmaxf(d / (stdv + EPS_M) * H_SCALE, -1.0f), 1.0f);
    g_gang[tid] = -M_MARGIN * ms;
    g_gadd[tid] = M_MARGIN + M_MARGIN * ms;
}

__global__ void label_kernel(const float* __restrict__ x,
                             const int* __restrict__ labels,
                             const float* __restrict__ w) {
    int i = blockIdx.x, tid = threadIdx.x;            // 128 threads
    int l = labels[i];
    l = max(0, min(l, NCLS - 1));                     // safety clamp
    const float4* xr = (const float4*)(x + (size_t)i * DDIM);
    const float4* wr = (const float4*)(w + (size_t)l * DDIM);
    float4 a = xr[tid], b = wr[tid];
    float dot = a.x*b.x + a.y*b.y + a.z*b.z + a.w*b.w;
    float wsq = b.x*b.x + b.y*b.y + b.z*b.z + b.w*b.w;
    __shared__ float rd[4], rw[4];
    dot = warpReduceSum(dot);
    wsq = warpReduceSum(wsq);
    if ((tid & 31) == 0) { rd[tid >> 5] = dot; rw[tid >> 5] = wsq; }
    __syncthreads();
    if (tid == 0) {
        float Dv = rd[0] + rd[1] + rd[2] + rd[3];
        float Wv = rw[0] + rw[1] + rw[2] + rw[3];
        float xn = fmaxf(g_xnorm[i], 1e-12f);
        float wn = fmaxf(sqrtf(Wv), 1e-12f);
        float c  = fminf(fmaxf(Dv / (xn * wn), -1.0f), 1.0f);
        float th = acosf(c);
        float plain = S_SCALE * cosf(fminf(fmaxf(th, EPS_M), PI_F - EPS_M));
        float thm = fminf(fmaxf(th + g_gang[i], EPS_M), PI_F - EPS_M);
        float adj = S_SCALE * (cosf(thm) - g_gadd[i]);
        g_lab_plain[i] = plain;
        g_lab_adj[i]   = adj;
    }
}

// ---------------- main fused f16 GEMM (f16 accumulate) + online LSE ----------------
__global__ void __launch_bounds__(256, 2) gemm_lse_kernel() {
    // grid: (8 m-tiles, 553 c-tiles); x fast so concurrent CTAs share B tiles in L2
    int mt = blockIdx.x, ct = blockIdx.y;
    int tid = threadIdx.x;
    int lane = tid & 31, warp = tid >> 5;
    int wm = warp & 3;        // 0..3 -> m offset
    int wn = warp >> 2;       // 0..1 -> n offset

    __shared__ __align__(16) __half sA[2][BM][BK + PAD];
    __shared__ __align__(16) __half sB[2][BN][BK + PAD];
    __shared__ float sMax[2][BM];
    __shared__ float sSum[2][BM];

    const int m0 = mt * BM;
    const int n0 = ct * BN;

    // f16 accumulators: per (mi,ni) two u32 regs, each packing 2 halves
    uint32_t acc[2][8][2];
#pragma unroll
    for (int i = 0; i < 2; i++)
#pragma unroll
        for (int j = 0; j < 8; j++) { acc[i][j][0] = 0u; acc[i][j][1] = 0u; }

    // loaders: each thread moves 2x16B for A and 2x16B for B per K-tile
    int ar = tid >> 2;            // 0..63
    int ac = (tid & 3) * 8;       // 0,8,16,24 (f16 elements)
    const __half* gA = g_A + (size_t)(m0 + ar) * DDIM + ac;
    const __half* gB = g_W + (size_t)(n0 + ar) * DDIM + ac;

#define LOAD_TILE(buf, kt) do {                                             \
        int _k0 = (kt) * BK;                                                \
        cp16(smem_u32(&sA[buf][ar     ][ac]), gA + _k0);                    \
        cp16(smem_u32(&sA[buf][ar + 64][ac]), gA + (size_t)64*DDIM + _k0);  \
        cp16(smem_u32(&sB[buf][ar     ][ac]), gB + _k0);                    \
        cp16(smem_u32(&sB[buf][ar + 64][ac]), gB + (size_t)64*DDIM + _k0);  \
        asm volatile("cp.async.commit_group;\n" ::);                        \
    } while (0)

    LOAD_TILE(0, 0);

    for (int kt = 0; kt < NKT; kt++) {
        if (kt + 1 < NKT) LOAD_TILE((kt + 1) & 1, kt + 1);
        else asm volatile("cp.async.commit_group;\n" ::);   // empty group so wait 1 == tile done
        asm volatile("cp.async.wait_group 1;\n" ::: "memory");
        __syncthreads();

        int buf = kt & 1;
#pragma unroll
        for (int kk = 0; kk < 2; kk++) {
            int kb = kk * 16 + (lane >> 4) * 8;
            uint32_t a_r[2][4];
#pragma unroll
            for (int mi = 0; mi < 2; mi++) {
                uint32_t addr = smem_u32(&sA[buf][wm*32 + mi*16 + (lane & 15)][kb]);
                asm volatile("ldmatrix.sync.aligned.m8n8.x4.shared.b16 {%0,%1,%2,%3}, [%4];"
                             : "=r"(a_r[mi][0]), "=r"(a_r[mi][1]), "=r"(a_r[mi][2]), "=r"(a_r[mi][3])
                             : "r"(addr));
            }
            uint32_t b_r[8][2];
#pragma unroll
            for (int nj = 0; nj < 4; nj++) {
                uint32_t addr = smem_u32(&sB[buf][wn*64 + nj*16 + (lane & 15)][kb]);
                uint32_t r0, r1, r2, r3;
                asm volatile("ldmatrix.sync.aligned.m8n8.x4.shared.b16 {%0,%1,%2,%3}, [%4];"
                             : "=r"(r0), "=r"(r1), "=r"(r2), "=r"(r3)
                             : "r"(addr));
                b_r[2*nj][0] = r0; b_r[2*nj+1][0] = r1;
                b_r[2*nj][1] = r2; b_r[2*nj+1][1] = r3;
            }
#pragma unroll
            for (int mi = 0; mi < 2; mi++)
#pragma unroll
                for (int ni = 0; ni < 8; ni++) {
                    asm volatile(
                        "mma.sync.aligned.m16n8k16.row.col.f16.f16.f16.f16 "
                        "{%0,%1}, {%2,%3,%4,%5}, {%6,%7}, {%0,%1};"
                        : "+r"(acc[mi][ni][0]), "+r"(acc[mi][ni][1])
                        : "r"(a_r[mi][0]), "r"(a_r[mi][1]), "r"(a_r[mi][2]), "r"(a_r[mi][3]),
                          "r"(b_r[ni][0]), "r"(b_r[ni][1]));
                }
        }
        __syncthreads();
    }
#undef LOAD_TILE

    // ---- epilogue: unpack f16 acc -> clamp -> logits -> per-row online (max, sumexp) ----
#pragma unroll
    for (int mi = 0; mi < 2; mi++) {
#pragma unroll
        for (int half = 0; half < 2; half++) {          // half selects row group (+8)
            int rw = wm*32 + mi*16 + half*8 + (lane >> 2);     // row within CTA
            float mx = -1e30f;
            float lg[8][2];
#pragma unroll
            for (int ni = 0; ni < 8; ni++) {
                float2 f = __half22float2(*(__half2*)&acc[mi][ni][half]);
                float v0 = S_SCALE * fminf(fmaxf(f.x, -COS_CLIP), COS_CLIP);
                float v1 = S_SCALE * fminf(fmaxf(f.y, -COS_CLIP), COS_CLIP);
                lg[ni][0] = v0; lg[ni][1] = v1;
                mx = fmaxf(mx, fmaxf(v0, v1));
            }
            float sm = 0.0f;
#pragma unroll
            for (int ni = 0; ni < 8; ni++) {
                sm += __expf(lg[ni][0] - mx);
                sm += __expf(lg[ni][1] - mx);
            }
            // reduce across the 4 lanes of the quad (they share the same row)
#pragma unroll
            for (int o = 1; o < 4; o <<= 1) {
                float om = __shfl_xor_sync(0xffffffffu, mx, o);
                float os = __shfl_xor_sync(0xffffffffu, sm, o);
                lse_combine(mx, sm, om, os);
            }
            if ((lane & 3) == 0) { sMax[wn][rw] = mx; sSum[wn][rw] = sm; }
        }
    }
    __syncthreads();

    if (tid < BM) {
        float m = sMax[0][tid], s = sSum[0][tid];
        lse_combine(m, s, sMax[1][tid], sSum[1][tid]);
        int grow = m0 + tid;
        g_pmax[(size_t)grow * NT + ct] = m;
        g_psum[(size_t)grow * NT + ct] = s;
    }
}

// ---------------- final reductions ----------------
__global__ void reduce1_kernel() {
    int row = blockIdx.x, tid = threadIdx.x;   // 128 threads
    float mx = -1e30f, sm = 0.0f;
    for (int t = tid; t < NT; t += 128) {
        float m = g_pmax[(size_t)row * NT + t];
        float s = g_psum[(size_t)row * NT + t];
        lse_combine(mx, sm, m, s);
    }
#pragma unroll
    for (int o = 16; o > 0; o >>= 1) {
        float om = __shfl_xor_sync(0xffffffffu, mx, o);
        float os = __shfl_xor_sync(0xffffffffu, sm, o);
        lse_combine(mx, sm, om, os);
    }
    __shared__ float rm[4], rs[4];
    int lane = tid & 31, w = tid >> 5;
    if (lane == 0) { rm[w] = mx; rs[w] = sm; }
    __syncthreads();
    if (tid == 0) {
        float m = rm[0], s = rs[0];
        lse_combine(m, s, rm[1], rs[1]);
        lse_combine(m, s, rm[2], rs[2]);
        lse_combine(m, s, rm[3], rs[3]);
        // remove PADC padding terms (logit exactly 0), swap plain->adjusted label term
        float plain = g_lab_plain[row], adj = g_lab_adj[row];
        float s2 = s - (float)PADC * __expf(0.0f - m) - __expf(plain - m) + __expf(adj - m);
        float lse = m + __logf(s2);
        g_loss[row] = lse - adj;
    }
}

__global__ void reduce2_kernel(float* __restrict__ out) {
    int tid = threadIdx.x;    // 256 threads
    float s = 0.0f;
    for (int t = tid; t < NROWS; t += 256) s += g_loss[t];
    s = warpReduceSum(s);
    __shared__ float red[8];
    if ((tid & 31) == 0) red[tid >> 5] = s;
    __syncthreads();
    if (tid == 0) {
        float tot = 0.0f;
        for (int i = 0; i < 8; i++) tot += red[i];
        out[0] = tot / (float)NROWS;
    }
}

// ---------------- launch ----------------
extern "C" void kernel_launch(void* const* d_in, const int* in_sizes, int n_in,
                              void* d_out, int out_size) {
    const float* x      = (const float*)d_in[0];
    const int*   labels = (const int*)d_in[1];
    const float* w      = (const float*)d_in[2];
    float* out = (float*)d_out;

    // order chosen so the GEMM sits at the ncu capture slot
    prep_x_kernel<<<NROWS, 128>>>(x);
    prep_w_kernel<<<CPAD, 128>>>(w);
    stats_kernel<<<1, 1024>>>();
    gemm_lse_kernel<<<dim3(8, NT), 256>>>();
    label_kernel<<<NROWS, 128>>>(x, labels, w);
    reduce1_kernel<<<NROWS, 128>>>();
    reduce2_kernel<<<1, 256>>>(out);
}

// round 6
// speedup vs baseline: 1.8558x; 1.0706x over previous
#include <cuda_runtime.h>
#include <cuda_fp16.h>
#include <cstdint>
#include <math.h>

// Problem constants
#define NROWS 1024
#define DDIM  512
#define NCLS  70722
#define NT    553            // ceil(NCLS/128)
#define CPAD  (NT*128)       // 70784
#define PADC  (CPAD - NCLS)  // 62 zero padding classes (logit exactly 0)
#define M_MARGIN 0.4f
#define H_SCALE  0.333f
#define S_SCALE  64.0f
#define EPS_M    0.001f
#define PI_F     3.14159265358979f
#define LOG2E64  92.332482616893f   // 64 * log2(e)

// GEMM tiling (f16, HMMA m16n8k16, f16 accumulate)
#define BM 128
#define BN 128
#define BK 32                 // f16 elements per k-tile
#define PAD 8
#define NKT (DDIM/BK)         // 16

// ---------------- device scratch (static: no allocations) ----------------
__device__ __half g_A[NROWS*DDIM];               // normalized x, f16
__device__ __half g_W[(size_t)CPAD*DDIM];        // normalized weights, f16 (~72.5MB)
__device__ float g_xnorm[NROWS];
__device__ float g_gang[NROWS];
__device__ float g_gadd[NROWS];
__device__ float g_pmax[(size_t)NROWS*NT];
__device__ float g_psum[(size_t)NROWS*NT];
__device__ float g_lab_plain[NROWS];
__device__ float g_lab_adj[NROWS];
__device__ float g_loss[NROWS];

// ---------------- helpers ----------------
__device__ __forceinline__ float warpReduceSum(float v) {
#pragma unroll
    for (int o = 16; o > 0; o >>= 1) v += __shfl_xor_sync(0xffffffffu, v, o);
    return v;
}
__device__ __forceinline__ uint32_t smem_u32(const void* p) {
    return (uint32_t)__cvta_generic_to_shared(p);
}
__device__ __forceinline__ void cp16(uint32_t s, const void* g) {
    asm volatile("cp.async.cg.shared.global [%0], [%1], 16;\n" :: "r"(s), "l"(g));
}
__device__ __forceinline__ void lse_combine(float& m, float& s, float om, float os) {
    float nm = fmaxf(m, om);
    s = s * __expf(m - nm) + os * __expf(om - nm);
    m = nm;
}
__device__ __forceinline__ __half2 ex2_h2(__half2 a) {
    uint32_t au = *(uint32_t*)&a, ru;
    asm("ex2.approx.f16x2 %0, %1;" : "=r"(ru) : "r"(au));
    return *(__half2*)&ru;
}

// ---------------- prep kernels ----------------
__global__ void prep_x_kernel(const float* __restrict__ x) {
    int row = blockIdx.x, tid = threadIdx.x;          // 128 threads
    const float4* xr = (const float4*)(x + (size_t)row * DDIM);
    float4 v = xr[tid];
    float s = v.x*v.x + v.y*v.y + v.z*v.z + v.w*v.w;
    __shared__ float red[4];
    s = warpReduceSum(s);
    if ((tid & 31) == 0) red[tid >> 5] = s;
    __syncthreads();
    float tot = red[0] + red[1] + red[2] + red[3];
    float nrm = sqrtf(tot);
    if (tid == 0) g_xnorm[row] = nrm;
    float inv = 1.0f / fmaxf(nrm, 1e-12f);
    __half2 h0 = __floats2half2_rn(v.x*inv, v.y*inv);
    __half2 h1 = __floats2half2_rn(v.z*inv, v.w*inv);
    uint2 pk; pk.x = *(unsigned*)&h0; pk.y = *(unsigned*)&h1;
    ((uint2*)g_A)[(size_t)row * (DDIM/4) + tid] = pk;
}

__global__ void prep_w_kernel(const float* __restrict__ w) {
    int row = blockIdx.x, tid = threadIdx.x;          // 128 threads, CPAD blocks
    uint2 pk;
    if (row < NCLS) {
        const float4* wr = (const float4*)(w + (size_t)row * DDIM);
        float4 v = wr[tid];
        float s = v.x*v.x + v.y*v.y + v.z*v.z + v.w*v.w;
        __shared__ float red[4];
        s = warpReduceSum(s);
        if ((tid & 31) == 0) red[tid >> 5] = s;
        __syncthreads();
        float tot = red[0] + red[1] + red[2] + red[3];
        float inv = 1.0f / fmaxf(sqrtf(tot), 1e-12f);
        __half2 h0 = __floats2half2_rn(v.x*inv, v.y*inv);
        __half2 h1 = __floats2half2_rn(v.z*inv, v.w*inv);
        pk.x = *(unsigned*)&h0; pk.y = *(unsigned*)&h1;
    } else {
        pk.x = 0u; pk.y = 0u;    // zero rows -> logit exactly 0, corrected in reduce1
    }
    ((uint2*)g_W)[(size_t)row * (DDIM/4) + tid] = pk;
}

__global__ void stats_kernel() {
    int tid = threadIdx.x;                            // 1024 threads
    float n = g_xnorm[tid];
    float s = fminf(fmaxf(fmaxf(n, 1e-8f), 0.001f), 100.0f);
    __shared__ float red[32];
    float t = warpReduceSum(s);
    if ((tid & 31) == 0) red[tid >> 5] = t;
    __syncthreads();
    if (tid < 32) { float v = red[tid]; v = warpReduceSum(v); if (tid == 0) red[0] = v; }
    __syncthreads();
    float mean = red[0] / (float)NROWS;
    float d = s - mean;
    __syncthreads();
    t = warpReduceSum(d * d);
    if ((tid & 31) == 0) red[tid >> 5] = t;
    __syncthreads();
    if (tid < 32) { float v = red[tid]; v = warpReduceSum(v); if (tid == 0) red[0] = v; }
    __syncthreads();
    float stdv = sqrtf(red[0] / (float)(NROWS - 1));   // ddof=1
    float ms = fminf(fmaxf(d / (stdv + EPS_M) * H_SCALE, -1.0f), 1.0f);
    g_gang[tid] = -M_MARGIN * ms;
    g_gadd[tid] = M_MARGIN + M_MARGIN * ms;
}

__global__ void label_kernel(const float* __restrict__ x,
                             const int* __restrict__ labels,
                             const float* __restrict__ w) {
    int i = blockIdx.x, tid = threadIdx.x;            // 128 threads
    int l = labels[i];
    l = max(0, min(l, NCLS - 1));                     // safety clamp
    const float4* xr = (const float4*)(x + (size_t)i * DDIM);
    const float4* wr = (const float4*)(w + (size_t)l * DDIM);
    float4 a = xr[tid], b = wr[tid];
    float dot = a.x*b.x + a.y*b.y + a.z*b.z + a.w*b.w;
    float wsq = b.x*b.x + b.y*b.y + b.z*b.z + b.w*b.w;
    __shared__ float rd[4], rw[4];
    dot = warpReduceSum(dot);
    wsq = warpReduceSum(wsq);
    if ((tid & 31) == 0) { rd[tid >> 5] = dot; rw[tid >> 5] = wsq; }
    __syncthreads();
    if (tid == 0) {
        float Dv = rd[0] + rd[1] + rd[2] + rd[3];
        float Wv = rw[0] + rw[1] + rw[2] + rw[3];
        float xn = fmaxf(g_xnorm[i], 1e-12f);
        float wn = fmaxf(sqrtf(Wv), 1e-12f);
        float c  = fminf(fmaxf(Dv / (xn * wn), -1.0f), 1.0f);
        float th = acosf(c);
        float plain = S_SCALE * cosf(fminf(fmaxf(th, EPS_M), PI_F - EPS_M));
        float thm = fminf(fmaxf(th + g_gang[i], EPS_M), PI_F - EPS_M);
        float adj = S_SCALE * (cosf(thm) - g_gadd[i]);
        g_lab_plain[i] = plain;
        g_lab_adj[i]   = adj;
    }
}

// ---------------- main fused f16 GEMM (f16 accumulate) + online LSE ----------------
__global__ void __launch_bounds__(256, 2) gemm_lse_kernel() {
    // grid: (8 m-tiles, 553 c-tiles); x fast so concurrent CTAs share B tiles in L2
    int mt = blockIdx.x, ct = blockIdx.y;
    int tid = threadIdx.x;
    int lane = tid & 31, warp = tid >> 5;
    int wm = warp & 3;        // 0..3 -> m offset
    int wn = warp >> 2;       // 0..1 -> n offset

    __shared__ __align__(16) __half sA[2][BM][BK + PAD];
    __shared__ __align__(16) __half sB[2][BN][BK + PAD];
    __shared__ float sMax[2][BM];
    __shared__ float sSum[2][BM];

    const int m0 = mt * BM;
    const int n0 = ct * BN;

    // f16 accumulators: per (mi,ni) two u32 regs, each packing 2 halves
    uint32_t acc[2][8][2];
#pragma unroll
    for (int i = 0; i < 2; i++)
#pragma unroll
        for (int j = 0; j < 8; j++) { acc[i][j][0] = 0u; acc[i][j][1] = 0u; }

    // loaders: each thread moves 2x16B for A and 2x16B for B per K-tile
    int ar = tid >> 2;            // 0..63
    int ac = (tid & 3) * 8;       // 0,8,16,24 (f16 elements)
    const __half* gA = g_A + (size_t)(m0 + ar) * DDIM + ac;
    const __half* gB = g_W + (size_t)(n0 + ar) * DDIM + ac;

#define LOAD_TILE(buf, kt) do {                                             \
        int _k0 = (kt) * BK;                                                \
        cp16(smem_u32(&sA[buf][ar     ][ac]), gA + _k0);                    \
        cp16(smem_u32(&sA[buf][ar + 64][ac]), gA + (size_t)64*DDIM + _k0);  \
        cp16(smem_u32(&sB[buf][ar     ][ac]), gB + _k0);                    \
        cp16(smem_u32(&sB[buf][ar + 64][ac]), gB + (size_t)64*DDIM + _k0);  \
        asm volatile("cp.async.commit_group;\n" ::);                        \
    } while (0)

    LOAD_TILE(0, 0);

    for (int kt = 0; kt < NKT; kt++) {
        if (kt + 1 < NKT) LOAD_TILE((kt + 1) & 1, kt + 1);
        else asm volatile("cp.async.commit_group;\n" ::);   // empty group so wait 1 == tile done
        asm volatile("cp.async.wait_group 1;\n" ::: "memory");
        __syncthreads();

        int buf = kt & 1;
#pragma unroll
        for (int kk = 0; kk < 2; kk++) {
            int kb = kk * 16 + (lane >> 4) * 8;
            uint32_t a_r[2][4];
#pragma unroll
            for (int mi = 0; mi < 2; mi++) {
                uint32_t addr = smem_u32(&sA[buf][wm*32 + mi*16 + (lane & 15)][kb]);
                asm volatile("ldmatrix.sync.aligned.m8n8.x4.shared.b16 {%0,%1,%2,%3}, [%4];"
                             : "=r"(a_r[mi][0]), "=r"(a_r[mi][1]), "=r"(a_r[mi][2]), "=r"(a_r[mi][3])
                             : "r"(addr));
            }
            uint32_t b_r[8][2];
#pragma unroll
            for (int nj = 0; nj < 4; nj++) {
                uint32_t addr = smem_u32(&sB[buf][wn*64 + nj*16 + (lane & 15)][kb]);
                uint32_t r0, r1, r2, r3;
                asm volatile("ldmatrix.sync.aligned.m8n8.x4.shared.b16 {%0,%1,%2,%3}, [%4];"
                             : "=r"(r0), "=r"(r1), "=r"(r2), "=r"(r3)
                             : "r"(addr));
                b_r[2*nj][0] = r0; b_r[2*nj+1][0] = r1;
                b_r[2*nj][1] = r2; b_r[2*nj+1][1] = r3;
            }
#pragma unroll
            for (int mi = 0; mi < 2; mi++)
#pragma unroll
                for (int ni = 0; ni < 8; ni++) {
                    asm volatile(
                        "mma.sync.aligned.m16n8k16.row.col.f16.f16.f16.f16 "
                        "{%0,%1}, {%2,%3,%4,%5}, {%6,%7}, {%0,%1};"
                        : "+r"(acc[mi][ni][0]), "+r"(acc[mi][ni][1])
                        : "r"(a_r[mi][0]), "r"(a_r[mi][1]), "r"(a_r[mi][2]), "r"(a_r[mi][3]),
                          "r"(b_r[ni][0]), "r"(b_r[ni][1]));
                }
        }
        __syncthreads();
    }
#undef LOAD_TILE

    // ---- epilogue: packed f16x2 clamp -> max -> ex2.f16x2 -> sum ----
    const __half2 h2hi = __float2half2_rn(1.0f);
    const __half2 h2lo = __float2half2_rn(-1.0f);
    const __half2 k2   = __float2half2_rn(LOG2E64);
#pragma unroll
    for (int mi = 0; mi < 2; mi++) {
#pragma unroll
        for (int hf = 0; hf < 2; hf++) {            // hf selects row group (+8)
            int rw = wm*32 + mi*16 + hf*8 + (lane >> 2);     // row within CTA
            __half2 v[8];
#pragma unroll
            for (int ni = 0; ni < 8; ni++) {
                __half2 c2 = *(__half2*)&acc[mi][ni][hf];
                v[ni] = __hmin2(__hmax2(c2, h2lo), h2hi);
            }
            // per-thread max (cosine units)
            __half2 m01 = __hmax2(v[0], v[1]), m23 = __hmax2(v[2], v[3]);
            __half2 m45 = __hmax2(v[4], v[5]), m67 = __hmax2(v[6], v[7]);
            __half2 m03 = __hmax2(m01, m23),   m47 = __hmax2(m45, m67);
            __half2 m2  = __hmax2(m03, m47);
            float mx = fmaxf(__low2float(m2), __high2float(m2));
            // quad max (4 lanes share the row)
            mx = fmaxf(mx, __shfl_xor_sync(0xffffffffu, mx, 1));
            mx = fmaxf(mx, __shfl_xor_sync(0xffffffffu, mx, 2));
            // exp2(log2e * (64c - 64mx)) pairs
            __half2 noff = __float2half2_rn(-LOG2E64 * mx);
            __half2 e[8];
#pragma unroll
            for (int ni = 0; ni < 8; ni++)
                e[ni] = ex2_h2(__hfma2(v[ni], k2, noff));
            __half2 s01 = __hadd2(e[0], e[1]), s23 = __hadd2(e[2], e[3]);
            __half2 s45 = __hadd2(e[4], e[5]), s67 = __hadd2(e[6], e[7]);
            __half2 s03 = __hadd2(s01, s23),   s47 = __hadd2(s45, s67);
            __half2 st  = __hadd2(s03, s47);
            float s = __low2float(st) + __high2float(st);
            // quad sum (same max on all 4 lanes)
            s += __shfl_xor_sync(0xffffffffu, s, 1);
            s += __shfl_xor_sync(0xffffffffu, s, 2);
            if ((lane & 3) == 0) { sMax[wn][rw] = S_SCALE * mx; sSum[wn][rw] = s; }
        }
    }
    __syncthreads();

    if (tid < BM) {
        float m = sMax[0][tid], s = sSum[0][tid];
        lse_combine(m, s, sMax[1][tid], sSum[1][tid]);
        int grow = m0 + tid;
        g_pmax[(size_t)grow * NT + ct] = m;
        g_psum[(size_t)grow * NT + ct] = s;
    }
}

// ---------------- final reductions ----------------
__global__ void reduce1_kernel() {
    int row = blockIdx.x, tid = threadIdx.x;   // 128 threads
    float mx = -1e30f, sm = 0.0f;
    for (int t = tid; t < NT; t += 128) {
        float m = g_pmax[(size_t)row * NT + t];
        float s = g_psum[(size_t)row * NT + t];
        lse_combine(mx, sm, m, s);
    }
#pragma unroll
    for (int o = 16; o > 0; o >>= 1) {
        float om = __shfl_xor_sync(0xffffffffu, mx, o);
        float os = __shfl_xor_sync(0xffffffffu, sm, o);
        lse_combine(mx, sm, om, os);
    }
    __shared__ float rm[4], rs[4];
    int lane = tid & 31, w = tid >> 5;
    if (lane == 0) { rm[w] = mx; rs[w] = sm; }
    __syncthreads();
    if (tid == 0) {
        float m = rm[0], s = rs[0];
        lse_combine(m, s, rm[1], rs[1]);
        lse_combine(m, s, rm[2], rs[2]);
        lse_combine(m, s, rm[3], rs[3]);
        // remove PADC padding terms (logit exactly 0), swap plain->adjusted label term
        float plain = g_lab_plain[row], adj = g_lab_adj[row];
        float s2 = s - (float)PADC * __expf(0.0f - m) - __expf(plain - m) + __expf(adj - m);
        float lse = m + __logf(s2);
        g_loss[row] = lse - adj;
    }
}

__global__ void reduce2_kernel(float* __restrict__ out) {
    int tid = threadIdx.x;    // 256 threads
    float s = 0.0f;
    for (int t = tid; t < NROWS; t += 256) s += g_loss[t];
    s = warpReduceSum(s);
    __shared__ float red[8];
    if ((tid & 31) == 0) red[tid >> 5] = s;
    __syncthreads();
    if (tid == 0) {
        float tot = 0.0f;
        for (int i = 0; i < 8; i++) tot += red[i];
        out[0] = tot / (float)NROWS;
    }
}

// ---------------- launch ----------------
extern "C" void kernel_launch(void* const* d_in, const int* in_sizes, int n_in,
                              void* d_out, int out_size) {
    const float* x      = (const float*)d_in[0];
    const int*   labels = (const int*)d_in[1];
    const float* w      = (const float*)d_in[2];
    float* out = (float*)d_out;

    // order chosen so the GEMM sits at the ncu capture slot
    prep_x_kernel<<<NROWS, 128>>>(x);
    prep_w_kernel<<<CPAD, 128>>>(w);
    stats_kernel<<<1, 1024>>>();
    gemm_lse_kernel<<<dim3(8, NT), 256>>>();
    label_kernel<<<NROWS, 128>>>(x, labels, w);
    reduce1_kernel<<<NROWS, 128>>>();
    reduce2_kernel<<<1, 256>>>(out);
}

// round 7
// speedup vs baseline: 1.9811x; 1.0675x over previous
#include <cuda_runtime.h>
#include <cuda_fp16.h>
#include <cstdint>
#include <math.h>

// Problem constants
#define NROWS 1024
#define DDIM  512
#define NCLS  70722
#define NT    553            // ceil(NCLS/128)
#define CPAD  (NT*128)       // 70784
#define PADC  (CPAD - NCLS)  // 62 zero padding classes (logit exactly 0)
#define M_MARGIN 0.4f
#define H_SCALE  0.333f
#define S_SCALE  64.0f
#define EPS_M    0.001f
#define PI_F     3.14159265358979f
#define LOG2E64  92.332482616893f   // 64 * log2(e)

// GEMM tiling (f16, HMMA m16n8k16, f16 accumulate)
#define BM 128
#define BN 128
#define BK 32                 // f16 elements per k-tile
#define PAD 8
#define ROWH (BK + PAD)       // 40 halfs per smem row
#define NKT (DDIM/BK)         // 16
#define NSTG 3

// dynamic smem layout (bytes)
#define A_ST   (BM*ROWH*2)            // 10240 per stage
#define SB_OFF (NSTG*A_ST)            // 30720
#define SMAX_OFF (2*NSTG*A_ST)        // 61440
#define SSUM_OFF (SMAX_OFF + 1024)
#define SMEM_TOTAL (SSUM_OFF + 1024)  // 63488

// ---------------- device scratch (static: no allocations) ----------------
__device__ __half g_A[NROWS*DDIM];               // normalized x, f16
__device__ __half g_W[(size_t)CPAD*DDIM];        // normalized weights, f16 (~72.5MB)
__device__ float g_xnorm[NROWS];
__device__ float g_gang[NROWS];
__device__ float g_gadd[NROWS];
__device__ float g_pmax[(size_t)NROWS*NT];
__device__ float g_psum[(size_t)NROWS*NT];
__device__ float g_lab_plain[NROWS];
__device__ float g_lab_adj[NROWS];
__device__ float g_loss[NROWS];

// ---------------- helpers ----------------
__device__ __forceinline__ float warpReduceSum(float v) {
#pragma unroll
    for (int o = 16; o > 0; o >>= 1) v += __shfl_xor_sync(0xffffffffu, v, o);
    return v;
}
__device__ __forceinline__ uint32_t smem_u32(const void* p) {
    return (uint32_t)__cvta_generic_to_shared(p);
}
__device__ __forceinline__ void cp16(uint32_t s, const void* g) {
    asm volatile("cp.async.cg.shared.global [%0], [%1], 16;\n" :: "r"(s), "l"(g));
}
__device__ __forceinline__ void lse_combine(float& m, float& s, float om, float os) {
    float nm = fmaxf(m, om);
    s = s * __expf(m - nm) + os * __expf(om - nm);
    m = nm;
}
__device__ __forceinline__ __half2 ex2_h2(__half2 a) {
    uint32_t au = *(uint32_t*)&a, ru;
    asm("ex2.approx.f16x2 %0, %1;" : "=r"(ru) : "r"(au));
    return *(__half2*)&ru;
}
__device__ __forceinline__ void ldmx4(uint32_t addr, uint32_t* r) {
    asm volatile("ldmatrix.sync.aligned.m8n8.x4.shared.b16 {%0,%1,%2,%3}, [%4];"
                 : "=r"(r[0]), "=r"(r[1]), "=r"(r[2]), "=r"(r[3]) : "r"(addr));
}

// ---------------- prep kernels ----------------
__global__ void prep_x_kernel(const float* __restrict__ x) {
    int row = blockIdx.x, tid = threadIdx.x;          // 128 threads
    const float4* xr = (const float4*)(x + (size_t)row * DDIM);
    float4 v = xr[tid];
    float s = v.x*v.x + v.y*v.y + v.z*v.z + v.w*v.w;
    __shared__ float red[4];
    s = warpReduceSum(s);
    if ((tid & 31) == 0) red[tid >> 5] = s;
    __syncthreads();
    float tot = red[0] + red[1] + red[2] + red[3];
    float nrm = sqrtf(tot);
    if (tid == 0) g_xnorm[row] = nrm;
    float inv = 1.0f / fmaxf(nrm, 1e-12f);
    __half2 h0 = __floats2half2_rn(v.x*inv, v.y*inv);
    __half2 h1 = __floats2half2_rn(v.z*inv, v.w*inv);
    uint2 pk; pk.x = *(unsigned*)&h0; pk.y = *(unsigned*)&h1;
    ((uint2*)g_A)[(size_t)row * (DDIM/4) + tid] = pk;
}

__global__ void prep_w_kernel(const float* __restrict__ w) {
    int row = blockIdx.x, tid = threadIdx.x;          // 128 threads, CPAD blocks
    uint2 pk;
    if (row < NCLS) {
        const float4* wr = (const float4*)(w + (size_t)row * DDIM);
        float4 v = wr[tid];
        float s = v.x*v.x + v.y*v.y + v.z*v.z + v.w*v.w;
        __shared__ float red[4];
        s = warpReduceSum(s);
        if ((tid & 31) == 0) red[tid >> 5] = s;
        __syncthreads();
        float tot = red[0] + red[1] + red[2] + red[3];
        float inv = 1.0f / fmaxf(sqrtf(tot), 1e-12f);
        __half2 h0 = __floats2half2_rn(v.x*inv, v.y*inv);
        __half2 h1 = __floats2half2_rn(v.z*inv, v.w*inv);
        pk.x = *(unsigned*)&h0; pk.y = *(unsigned*)&h1;
    } else {
        pk.x = 0u; pk.y = 0u;    // zero rows -> logit exactly 0, corrected in reduce1
    }
    ((uint2*)g_W)[(size_t)row * (DDIM/4) + tid] = pk;
}

__global__ void stats_kernel() {
    int tid = threadIdx.x;                            // 1024 threads
    float n = g_xnorm[tid];
    float s = fminf(fmaxf(fmaxf(n, 1e-8f), 0.001f), 100.0f);
    __shared__ float red[32];
    float t = warpReduceSum(s);
    if ((tid & 31) == 0) red[tid >> 5] = t;
    __syncthreads();
    if (tid < 32) { float v = red[tid]; v = warpReduceSum(v); if (tid == 0) red[0] = v; }
    __syncthreads();
    float mean = red[0] / (float)NROWS;
    float d = s - mean;
    __syncthreads();
    t = warpReduceSum(d * d);
    if ((tid & 31) == 0) red[tid >> 5] = t;
    __syncthreads();
    if (tid < 32) { float v = red[tid]; v = warpReduceSum(v); if (tid == 0) red[0] = v; }
    __syncthreads();
    float stdv = sqrtf(red[0] / (float)(NROWS - 1));   // ddof=1
    float ms = fminf(fmaxf(d / (stdv + EPS_M) * H_SCALE, -1.0f), 1.0f);
    g_gang[tid] = -M_MARGIN * ms;
    g_gadd[tid] = M_MARGIN + M_MARGIN * ms;
}

__global__ void label_kernel(const float* __restrict__ x,
                             const int* __restrict__ labels,
                             const float* __restrict__ w) {
    int i = blockIdx.x, tid = threadIdx.x;            // 128 threads
    int l = labels[i];
    l = max(0, min(l, NCLS - 1));                     // safety clamp
    const float4* xr = (const float4*)(x + (size_t)i * DDIM);
    const float4* wr = (const float4*)(w + (size_t)l * DDIM);
    float4 a = xr[tid], b = wr[tid];
    float dot = a.x*b.x + a.y*b.y + a.z*b.z + a.w*b.w;
    float wsq = b.x*b.x + b.y*b.y + b.z*b.z + b.w*b.w;
    __shared__ float rd[4], rw[4];
    dot = warpReduceSum(dot);
    wsq = warpReduceSum(wsq);
    if ((tid & 31) == 0) { rd[tid >> 5] = dot; rw[tid >> 5] = wsq; }
    __syncthreads();
    if (tid == 0) {
        float Dv = rd[0] + rd[1] + rd[2] + rd[3];
        float Wv = rw[0] + rw[1] + rw[2] + rw[3];
        float xn = fmaxf(g_xnorm[i], 1e-12f);
        float wn = fmaxf(sqrtf(Wv), 1e-12f);
        float c  = fminf(fmaxf(Dv / (xn * wn), -1.0f), 1.0f);
        float th = acosf(c);
        float plain = S_SCALE * cosf(fminf(fmaxf(th, EPS_M), PI_F - EPS_M));
        float thm = fminf(fmaxf(th + g_gang[i], EPS_M), PI_F - EPS_M);
        float adj = S_SCALE * (cosf(thm) - g_gadd[i]);
        g_lab_plain[i] = plain;
        g_lab_adj[i]   = adj;
    }
}

// ---------------- main fused f16 GEMM (f16 accumulate) + online LSE ----------------
__global__ void __launch_bounds__(256, 2) gemm_lse_kernel() {
    extern __shared__ __align__(16) char smem[];
    uint32_t sb = smem_u32(smem);
    float* sMax = (float*)(smem + SMAX_OFF);   // [2][BM]
    float* sSum = (float*)(smem + SSUM_OFF);   // [2][BM]

    int mt = blockIdx.x, ct = blockIdx.y;
    int tid = threadIdx.x;
    int lane = tid & 31, warp = tid >> 5;
    int wm = warp & 3;        // 0..3 -> m offset
    int wn = warp >> 2;       // 0..1 -> n offset

    const int m0 = mt * BM;
    const int n0 = ct * BN;

    // f16 accumulators: per (mi,ni) two u32 regs, each packing 2 halves
    uint32_t acc[2][8][2];
#pragma unroll
    for (int i = 0; i < 2; i++)
#pragma unroll
        for (int j = 0; j < 8; j++) { acc[i][j][0] = 0u; acc[i][j][1] = 0u; }

    // loaders: each thread moves 2x16B for A and 2x16B for B per K-tile
    int ar = tid >> 2;            // 0..63
    int ac = (tid & 3) * 8;       // 0,8,16,24 (f16 elements)
    const __half* gA = g_A + (size_t)(m0 + ar) * DDIM + ac;
    const __half* gB = g_W + (size_t)(n0 + ar) * DDIM + ac;

#define LOAD_TILE(stg, kt) do {                                                   \
        int _k0 = (kt) * BK;                                                      \
        uint32_t _a = sb + (stg) * A_ST + (ar * ROWH + ac) * 2;                   \
        uint32_t _b = sb + SB_OFF + (stg) * A_ST + (ar * ROWH + ac) * 2;          \
        cp16(_a,                 gA + _k0);                                       \
        cp16(_a + 64 * ROWH * 2, gA + (size_t)64*DDIM + _k0);                     \
        cp16(_b,                 gB + _k0);                                       \
        cp16(_b + 64 * ROWH * 2, gB + (size_t)64*DDIM + _k0);                     \
        asm volatile("cp.async.commit_group;\n" ::);                              \
    } while (0)

    // fragment loader: 2 A-ldmatrix + 4 B-ldmatrix for (stage, kk)
    int arow0 = wm * 32 + (lane & 15);       // A base row (+16 for mi=1)
    int brow0 = wn * 64 + (lane & 15);       // B base row (+16*nj)
#define LD_FRAGS(stg, kk, fa, fb) do {                                            \
        int _kb = (kk) * 16 + (lane >> 4) * 8;                                    \
        uint32_t _ab = sb + (stg) * A_ST + _kb * 2;                               \
        uint32_t _bb = sb + SB_OFF + (stg) * A_ST + _kb * 2;                      \
        ldmx4(_ab + (arow0      ) * ROWH * 2, (fa)[0]);                           \
        ldmx4(_ab + (arow0 + 16 ) * ROWH * 2, (fa)[1]);                           \
        uint32_t _t[4];                                                           \
        ldmx4(_bb + (brow0      ) * ROWH * 2, _t);                                \
        (fb)[0][0]=_t[0]; (fb)[1][0]=_t[1]; (fb)[0][1]=_t[2]; (fb)[1][1]=_t[3];   \
        ldmx4(_bb + (brow0 + 16 ) * ROWH * 2, _t);                                \
        (fb)[2][0]=_t[0]; (fb)[3][0]=_t[1]; (fb)[2][1]=_t[2]; (fb)[3][1]=_t[3];   \
        ldmx4(_bb + (brow0 + 32 ) * ROWH * 2, _t);                                \
        (fb)[4][0]=_t[0]; (fb)[5][0]=_t[1]; (fb)[4][1]=_t[2]; (fb)[5][1]=_t[3];   \
        ldmx4(_bb + (brow0 + 48 ) * ROWH * 2, _t);                                \
        (fb)[6][0]=_t[0]; (fb)[7][0]=_t[1]; (fb)[6][1]=_t[2]; (fb)[7][1]=_t[3];   \
    } while (0)

#define MMA_SET(fa, fb) do {                                                      \
        _Pragma("unroll")                                                         \
        for (int mi = 0; mi < 2; mi++)                                            \
            _Pragma("unroll")                                                     \
            for (int ni = 0; ni < 8; ni++) {                                      \
                asm volatile(                                                     \
                    "mma.sync.aligned.m16n8k16.row.col.f16.f16.f16.f16 "          \
                    "{%0,%1}, {%2,%3,%4,%5}, {%6,%7}, {%0,%1};"                   \
                    : "+r"(acc[mi][ni][0]), "+r"(acc[mi][ni][1])                  \
                    : "r"((fa)[mi][0]), "r"((fa)[mi][1]),                         \
                      "r"((fa)[mi][2]), "r"((fa)[mi][3]),                         \
                      "r"((fb)[ni][0]), "r"((fb)[ni][1]));                        \
            }                                                                     \
    } while (0)

    uint32_t fA0[2][4], fB0[8][2], fA1[2][4], fB1[8][2];

    LOAD_TILE(0, 0);
    LOAD_TILE(1, 1);
    asm volatile("cp.async.wait_group 1;\n" ::: "memory");
    __syncthreads();
    LD_FRAGS(0, 0, fA0, fB0);

    for (int kt = 0; kt < NKT; kt++) {
        int s = kt % NSTG;
        if (kt + 2 < NKT) LOAD_TILE((kt + 2) % NSTG, kt + 2);
        else asm volatile("cp.async.commit_group;\n" ::);
        LD_FRAGS(s, 1, fA1, fB1);          // kk=1 frags issued before kk=0 MMAs
        MMA_SET(fA0, fB0);
        MMA_SET(fA1, fB1);
        asm volatile("cp.async.wait_group 1;\n" ::: "memory");
        __syncthreads();
        if (kt + 1 < NKT) LD_FRAGS((kt + 1) % NSTG, 0, fA0, fB0);
    }
#undef LOAD_TILE
#undef LD_FRAGS
#undef MMA_SET

    // ---- epilogue: packed f16x2 clamp -> max -> ex2.f16x2 -> sum ----
    const __half2 h2hi = __float2half2_rn(1.0f);
    const __half2 h2lo = __float2half2_rn(-1.0f);
    const __half2 k2   = __float2half2_rn(LOG2E64);
#pragma unroll
    for (int mi = 0; mi < 2; mi++) {
#pragma unroll
        for (int hf = 0; hf < 2; hf++) {            // hf selects row group (+8)
            int rw = wm*32 + mi*16 + hf*8 + (lane >> 2);     // row within CTA
            __half2 v[8];
#pragma unroll
            for (int ni = 0; ni < 8; ni++) {
                __half2 c2 = *(__half2*)&acc[mi][ni][hf];
                v[ni] = __hmin2(__hmax2(c2, h2lo), h2hi);
            }
            __half2 m01 = __hmax2(v[0], v[1]), m23 = __hmax2(v[2], v[3]);
            __half2 m45 = __hmax2(v[4], v[5]), m67 = __hmax2(v[6], v[7]);
            __half2 m03 = __hmax2(m01, m23),   m47 = __hmax2(m45, m67);
            __half2 m2  = __hmax2(m03, m47);
            float mx = fmaxf(__low2float(m2), __high2float(m2));
            mx = fmaxf(mx, __shfl_xor_sync(0xffffffffu, mx, 1));
            mx = fmaxf(mx, __shfl_xor_sync(0xffffffffu, mx, 2));
            __half2 noff = __float2half2_rn(-LOG2E64 * mx);
            __half2 e[8];
#pragma unroll
            for (int ni = 0; ni < 8; ni++)
                e[ni] = ex2_h2(__hfma2(v[ni], k2, noff));
            __half2 s01 = __hadd2(e[0], e[1]), s23 = __hadd2(e[2], e[3]);
            __half2 s45 = __hadd2(e[4], e[5]), s67 = __hadd2(e[6], e[7]);
            __half2 s03 = __hadd2(s01, s23),   s47 = __hadd2(s45, s67);
            __half2 st  = __hadd2(s03, s47);
            float s = __low2float(st) + __high2float(st);
            s += __shfl_xor_sync(0xffffffffu, s, 1);
            s += __shfl_xor_sync(0xffffffffu, s, 2);
            if ((lane & 3) == 0) { sMax[wn*BM + rw] = S_SCALE * mx; sSum[wn*BM + rw] = s; }
        }
    }
    __syncthreads();

    if (tid < BM) {
        float m = sMax[tid], s = sSum[tid];
        lse_combine(m, s, sMax[BM + tid], sSum[BM + tid]);
        int grow = m0 + tid;
        g_pmax[(size_t)grow * NT + ct] = m;
        g_psum[(size_t)grow * NT + ct] = s;
    }
}

// ---------------- final reductions ----------------
__global__ void reduce1_kernel() {
    int row = blockIdx.x, tid = threadIdx.x;   // 128 threads
    float mx = -1e30f, sm = 0.0f;
    for (int t = tid; t < NT; t += 128) {
        float m = g_pmax[(size_t)row * NT + t];
        float s = g_psum[(size_t)row * NT + t];
        lse_combine(mx, sm, m, s);
    }
#pragma unroll
    for (int o = 16; o > 0; o >>= 1) {
        float om = __shfl_xor_sync(0xffffffffu, mx, o);
        float os = __shfl_xor_sync(0xffffffffu, sm, o);
        lse_combine(mx, sm, om, os);
    }
    __shared__ float rm[4], rs[4];
    int lane = tid & 31, w = tid >> 5;
    if (lane == 0) { rm[w] = mx; rs[w] = sm; }
    __syncthreads();
    if (tid == 0) {
        float m = rm[0], s = rs[0];
        lse_combine(m, s, rm[1], rs[1]);
        lse_combine(m, s, rm[2], rs[2]);
        lse_combine(m, s, rm[3], rs[3]);
        // remove PADC padding terms (logit exactly 0), swap plain->adjusted label term
        float plain = g_lab_plain[row], adj = g_lab_adj[row];
        float s2 = s - (float)PADC * __expf(0.0f - m) - __expf(plain - m) + __expf(adj - m);
        float lse = m + __logf(s2);
        g_loss[row] = lse - adj;
    }
}

__global__ void reduce2_kernel(float* __restrict__ out) {
    int tid = threadIdx.x;    // 256 threads
    float s = 0.0f;
    for (int t = tid; t < NROWS; t += 256) s += g_loss[t];
    s = warpReduceSum(s);
    __shared__ float red[8];
    if ((tid & 31) == 0) red[tid >> 5] = s;
    __syncthreads();
    if (tid == 0) {
        float tot = 0.0f;
        for (int i = 0; i < 8; i++) tot += red[i];
        out[0] = tot / (float)NROWS;
    }
}

// ---------------- launch ----------------
extern "C" void kernel_launch(void* const* d_in, const int* in_sizes, int n_in,
                              void* d_out, int out_size) {
    const float* x      = (const float*)d_in[0];
    const int*   labels = (const int*)d_in[1];
    const float* w      = (const float*)d_in[2];
    float* out = (float*)d_out;

    cudaFuncSetAttribute(gemm_lse_kernel, cudaFuncAttributeMaxDynamicSharedMemorySize, SMEM_TOTAL);

    // order chosen so the GEMM sits at the ncu capture slot
    prep_x_kernel<<<NROWS, 128>>>(x);
    prep_w_kernel<<<CPAD, 128>>>(w);
    stats_kernel<<<1, 1024>>>();
    gemm_lse_kernel<<<dim3(8, NT), 256, SMEM_TOTAL>>>();
    label_kernel<<<NROWS, 128>>>(x, labels, w);
    reduce1_kernel<<<NROWS, 128>>>();
    reduce2_kernel<<<1, 256>>>(out);
}

// round 8
// speedup vs baseline: 2.0101x; 1.0147x over previous
#include <cuda_runtime.h>
#include <cuda_fp16.h>
#include <cstdint>
#include <math.h>

// Problem constants
#define NROWS 1024
#define DDIM  512
#define NCLS  70722
#define NT    277            // ceil(NCLS/256)
#define CPAD  (NT*256)       // 70912
#define PADC  (CPAD - NCLS)  // 190 zero padding classes (logit exactly 0)
#define M_MARGIN 0.4f
#define H_SCALE  0.333f
#define S_SCALE  64.0f
#define EPS_M    0.001f
#define PI_F     3.14159265358979f
#define LOG2E64  92.332482616893f   // 64 * log2(e)

// GEMM tiling (f16, HMMA m16n8k16, f16 accumulate)
#define BM 128
#define BN 256
#define BK 32                 // f16 elements per k-tile
#define PAD 8
#define ROWH (BK + PAD)       // 40 halfs per smem row
#define NKT (DDIM/BK)         // 16
#define NSTG 3

// dynamic smem layout (bytes)
#define A_ST   (BM*ROWH*2)            // 10240 per stage
#define B_ST   (BN*ROWH*2)            // 20480 per stage
#define SB_OFF (NSTG*A_ST)            // 30720
#define SMAX_OFF (SB_OFF + NSTG*B_ST) // 92160
#define SSUM_OFF (SMAX_OFF + 4*BM*4)  // +2048
#define SMEM_TOTAL (SSUM_OFF + 4*BM*4)// 96256

// ---------------- device scratch (static: no allocations) ----------------
__device__ __half g_A[NROWS*DDIM];               // normalized x, f16
__device__ __half g_W[(size_t)CPAD*DDIM];        // normalized weights, f16 (~72.6MB)
__device__ float g_xnorm[NROWS];
__device__ float g_gang[NROWS];
__device__ float g_gadd[NROWS];
__device__ float g_pmax[(size_t)NROWS*NT];
__device__ float g_psum[(size_t)NROWS*NT];
__device__ float g_lab_plain[NROWS];
__device__ float g_lab_adj[NROWS];
__device__ float g_loss[NROWS];

// ---------------- helpers ----------------
__device__ __forceinline__ float warpReduceSum(float v) {
#pragma unroll
    for (int o = 16; o > 0; o >>= 1) v += __shfl_xor_sync(0xffffffffu, v, o);
    return v;
}
__device__ __forceinline__ uint32_t smem_u32(const void* p) {
    return (uint32_t)__cvta_generic_to_shared(p);
}
__device__ __forceinline__ void cp16(uint32_t s, const void* g) {
    asm volatile("cp.async.cg.shared.global [%0], [%1], 16;\n" :: "r"(s), "l"(g));
}
__device__ __forceinline__ void lse_combine(float& m, float& s, float om, float os) {
    float nm = fmaxf(m, om);
    s = s * __expf(m - nm) + os * __expf(om - nm);
    m = nm;
}
__device__ __forceinline__ __half2 ex2_h2(__half2 a) {
    uint32_t au = *(uint32_t*)&a, ru;
    asm("ex2.approx.f16x2 %0, %1;" : "=r"(ru) : "r"(au));
    return *(__half2*)&ru;
}
__device__ __forceinline__ void ldmx4(uint32_t addr, uint32_t* r) {
    asm volatile("ldmatrix.sync.aligned.m8n8.x4.shared.b16 {%0,%1,%2,%3}, [%4];"
                 : "=r"(r[0]), "=r"(r[1]), "=r"(r[2]), "=r"(r[3]) : "r"(addr));
}

// ---------------- prep kernels ----------------
__global__ void prep_x_kernel(const float* __restrict__ x) {
    int row = blockIdx.x, tid = threadIdx.x;          // 128 threads
    const float4* xr = (const float4*)(x + (size_t)row * DDIM);
    float4 v = xr[tid];
    float s = v.x*v.x + v.y*v.y + v.z*v.z + v.w*v.w;
    __shared__ float red[4];
    s = warpReduceSum(s);
    if ((tid & 31) == 0) red[tid >> 5] = s;
    __syncthreads();
    float tot = red[0] + red[1] + red[2] + red[3];
    float nrm = sqrtf(tot);
    if (tid == 0) g_xnorm[row] = nrm;
    float inv = 1.0f / fmaxf(nrm, 1e-12f);
    __half2 h0 = __floats2half2_rn(v.x*inv, v.y*inv);
    __half2 h1 = __floats2half2_rn(v.z*inv, v.w*inv);
    uint2 pk; pk.x = *(unsigned*)&h0; pk.y = *(unsigned*)&h1;
    ((uint2*)g_A)[(size_t)row * (DDIM/4) + tid] = pk;
}

__global__ void prep_w_kernel(const float* __restrict__ w) {
    int row = blockIdx.x, tid = threadIdx.x;          // 128 threads, CPAD blocks
    uint2 pk;
    if (row < NCLS) {
        const float4* wr = (const float4*)(w + (size_t)row * DDIM);
        float4 v = wr[tid];
        float s = v.x*v.x + v.y*v.y + v.z*v.z + v.w*v.w;
        __shared__ float red[4];
        s = warpReduceSum(s);
        if ((tid & 31) == 0) red[tid >> 5] = s;
        __syncthreads();
        float tot = red[0] + red[1] + red[2] + red[3];
        float inv = 1.0f / fmaxf(sqrtf(tot), 1e-12f);
        __half2 h0 = __floats2half2_rn(v.x*inv, v.y*inv);
        __half2 h1 = __floats2half2_rn(v.z*inv, v.w*inv);
        pk.x = *(unsigned*)&h0; pk.y = *(unsigned*)&h1;
    } else {
        pk.x = 0u; pk.y = 0u;    // zero rows -> logit exactly 0, corrected in reduce1
    }
    ((uint2*)g_W)[(size_t)row * (DDIM/4) + tid] = pk;
}

__global__ void stats_kernel() {
    int tid = threadIdx.x;                            // 1024 threads
    float n = g_xnorm[tid];
    float s = fminf(fmaxf(fmaxf(n, 1e-8f), 0.001f), 100.0f);
    __shared__ float red[32];
    float t = warpReduceSum(s);
    if ((tid & 31) == 0) red[tid >> 5] = t;
    __syncthreads();
    if (tid < 32) { float v = red[tid]; v = warpReduceSum(v); if (tid == 0) red[0] = v; }
    __syncthreads();
    float mean = red[0] / (float)NROWS;
    float d = s - mean;
    __syncthreads();
    t = warpReduceSum(d * d);
    if ((tid & 31) == 0) red[tid >> 5] = t;
    __syncthreads();
    if (tid < 32) { float v = red[tid]; v = warpReduceSum(v); if (tid == 0) red[0] = v; }
    __syncthreads();
    float stdv = sqrtf(red[0] / (float)(NROWS - 1));   // ddof=1
    float ms = fminf(fmaxf(d / (stdv + EPS_M) * H_SCALE, -1.0f), 1.0f);
    g_gang[tid] = -M_MARGIN * ms;
    g_gadd[tid] = M_MARGIN + M_MARGIN * ms;
}

__global__ void label_kernel(const float* __restrict__ x,
                             const int* __restrict__ labels,
                             const float* __restrict__ w) {
    int i = blockIdx.x, tid = threadIdx.x;            // 128 threads
    int l = labels[i];
    l = max(0, min(l, NCLS - 1));                     // safety clamp
    const float4* xr = (const float4*)(x + (size_t)i * DDIM);
    const float4* wr = (const float4*)(w + (size_t)l * DDIM);
    float4 a = xr[tid], b = wr[tid];
    float dot = a.x*b.x + a.y*b.y + a.z*b.z + a.w*b.w;
    float wsq = b.x*b.x + b.y*b.y + b.z*b.z + b.w*b.w;
    __shared__ float rd[4], rw[4];
    dot = warpReduceSum(dot);
    wsq = warpReduceSum(wsq);
    if ((tid & 31) == 0) { rd[tid >> 5] = dot; rw[tid >> 5] = wsq; }
    __syncthreads();
    if (tid == 0) {
        float Dv = rd[0] + rd[1] + rd[2] + rd[3];
        float Wv = rw[0] + rw[1] + rw[2] + rw[3];
        float xn = fmaxf(g_xnorm[i], 1e-12f);
        float wn = fmaxf(sqrtf(Wv), 1e-12f);
        float c  = fminf(fmaxf(Dv / (xn * wn), -1.0f), 1.0f);
        float th = acosf(c);
        float plain = S_SCALE * cosf(fminf(fmaxf(th, EPS_M), PI_F - EPS_M));
        float thm = fminf(fmaxf(th + g_gang[i], EPS_M), PI_F - EPS_M);
        float adj = S_SCALE * (cosf(thm) - g_gadd[i]);
        g_lab_plain[i] = plain;
        g_lab_adj[i]   = adj;
    }
}

// ---------------- main fused f16 GEMM (f16 accumulate) + online LSE ----------------
// CTA tile 128x256, warp tile 64x64 (8 warps: 2m x 4n)
__global__ void __launch_bounds__(256, 2) gemm_lse_kernel() {
    extern __shared__ __align__(16) char smem[];
    uint32_t sb = smem_u32(smem);
    float* sMax = (float*)(smem + SMAX_OFF);   // [4][BM]
    float* sSum = (float*)(smem + SSUM_OFF);   // [4][BM]

    int mt = blockIdx.x, ct = blockIdx.y;
    int tid = threadIdx.x;
    int lane = tid & 31, warp = tid >> 5;
    int wm = warp & 1;        // 0..1 -> m offset (64 each)
    int wn = warp >> 1;       // 0..3 -> n offset (64 each)

    const int m0 = mt * BM;
    const int n0 = ct * BN;

    // f16 accumulators: [mi=4][ni=8][2 halves-pairs]
    uint32_t acc[4][8][2];
#pragma unroll
    for (int i = 0; i < 4; i++)
#pragma unroll
        for (int j = 0; j < 8; j++) { acc[i][j][0] = 0u; acc[i][j][1] = 0u; }

    // loaders: each thread moves 2x16B for A and 4x16B for B per K-tile
    int ar = tid >> 2;            // 0..63
    int ac = (tid & 3) * 8;       // 0,8,16,24 (f16 elements)
    const __half* gA = g_A + (size_t)(m0 + ar) * DDIM + ac;
    const __half* gB = g_W + (size_t)(n0 + ar) * DDIM + ac;

#define LOAD_TILE(stg, kt) do {                                                   \
        int _k0 = (kt) * BK;                                                      \
        uint32_t _a = sb + (stg) * A_ST + (ar * ROWH + ac) * 2;                   \
        uint32_t _b = sb + SB_OFF + (stg) * B_ST + (ar * ROWH + ac) * 2;          \
        cp16(_a,                  gA + _k0);                                      \
        cp16(_a + 64*ROWH*2,      gA + (size_t)64*DDIM  + _k0);                   \
        cp16(_b,                  gB + _k0);                                      \
        cp16(_b + 64*ROWH*2,      gB + (size_t)64*DDIM  + _k0);                   \
        cp16(_b + 128*ROWH*2,     gB + (size_t)128*DDIM + _k0);                   \
        cp16(_b + 192*ROWH*2,     gB + (size_t)192*DDIM + _k0);                   \
        asm volatile("cp.async.commit_group;\n" ::);                              \
    } while (0)

    // fragment loaders for (stage, kk): A 4 x4-ldmatrix, B 4 x4-ldmatrix
    int arow0 = wm * 64 + (lane & 15);       // A base row (+16 per mi)
    int brow0 = wn * 64 + (lane & 15);       // B base row (+16 per nj-pair)
#define LD_FRAGS(stg, kk, fa, fb) do {                                            \
        int _kb = (kk) * 16 + (lane >> 4) * 8;                                    \
        uint32_t _ab = sb + (stg) * A_ST + _kb * 2;                               \
        uint32_t _bb = sb + SB_OFF + (stg) * B_ST + _kb * 2;                      \
        ldmx4(_ab + (arow0      ) * ROWH * 2, (fa)[0]);                           \
        ldmx4(_ab + (arow0 + 16 ) * ROWH * 2, (fa)[1]);                           \
        ldmx4(_ab + (arow0 + 32 ) * ROWH * 2, (fa)[2]);                           \
        ldmx4(_ab + (arow0 + 48 ) * ROWH * 2, (fa)[3]);                           \
        uint32_t _t[4];                                                           \
        ldmx4(_bb + (brow0      ) * ROWH * 2, _t);                                \
        (fb)[0][0]=_t[0]; (fb)[1][0]=_t[1]; (fb)[0][1]=_t[2]; (fb)[1][1]=_t[3];   \
        ldmx4(_bb + (brow0 + 16 ) * ROWH * 2, _t);                                \
        (fb)[2][0]=_t[0]; (fb)[3][0]=_t[1]; (fb)[2][1]=_t[2]; (fb)[3][1]=_t[3];   \
        ldmx4(_bb + (brow0 + 32 ) * ROWH * 2, _t);                                \
        (fb)[4][0]=_t[0]; (fb)[5][0]=_t[1]; (fb)[4][1]=_t[2]; (fb)[5][1]=_t[3];   \
        ldmx4(_bb + (brow0 + 48 ) * ROWH * 2, _t);                                \
        (fb)[6][0]=_t[0]; (fb)[7][0]=_t[1]; (fb)[6][1]=_t[2]; (fb)[7][1]=_t[3];   \
    } while (0)

#define MMA_SET(fa, fb) do {                                                      \
        _Pragma("unroll")                                                         \
        for (int mi = 0; mi < 4; mi++)                                            \
            _Pragma("unroll")                                                     \
            for (int ni = 0; ni < 8; ni++) {                                      \
                asm volatile(                                                     \
                    "mma.sync.aligned.m16n8k16.row.col.f16.f16.f16.f16 "          \
                    "{%0,%1}, {%2,%3,%4,%5}, {%6,%7}, {%0,%1};"                   \
                    : "+r"(acc[mi][ni][0]), "+r"(acc[mi][ni][1])                  \
                    : "r"((fa)[mi][0]), "r"((fa)[mi][1]),                         \
                      "r"((fa)[mi][2]), "r"((fa)[mi][3]),                         \
                      "r"((fb)[ni][0]), "r"((fb)[ni][1]));                        \
            }                                                                     \
    } while (0)

    uint32_t fA[4][4], fB[8][2];

    LOAD_TILE(0, 0);
    LOAD_TILE(1, 1);
    asm volatile("cp.async.wait_group 1;\n" ::: "memory");
    __syncthreads();

    for (int kt = 0; kt < NKT; kt++) {
        int s = kt % NSTG;
        if (kt + 2 < NKT) LOAD_TILE((kt + 2) % NSTG, kt + 2);
        else asm volatile("cp.async.commit_group;\n" ::);
        LD_FRAGS(s, 0, fA, fB);
        MMA_SET(fA, fB);
        LD_FRAGS(s, 1, fA, fB);
        MMA_SET(fA, fB);
        asm volatile("cp.async.wait_group 1;\n" ::: "memory");
        __syncthreads();
    }
#undef LOAD_TILE
#undef LD_FRAGS
#undef MMA_SET

    // ---- epilogue: packed f16x2 clamp -> max -> ex2.f16x2 -> sum ----
    const __half2 h2hi = __float2half2_rn(1.0f);
    const __half2 h2lo = __float2half2_rn(-1.0f);
    const __half2 k2   = __float2half2_rn(LOG2E64);
#pragma unroll
    for (int mi = 0; mi < 4; mi++) {
#pragma unroll
        for (int hf = 0; hf < 2; hf++) {            // hf selects row group (+8)
            int rw = wm*64 + mi*16 + hf*8 + (lane >> 2);     // row within CTA
            __half2 v[8];
#pragma unroll
            for (int ni = 0; ni < 8; ni++) {
                __half2 c2 = *(__half2*)&acc[mi][ni][hf];
                v[ni] = __hmin2(__hmax2(c2, h2lo), h2hi);
            }
            __half2 m01 = __hmax2(v[0], v[1]), m23 = __hmax2(v[2], v[3]);
            __half2 m45 = __hmax2(v[4], v[5]), m67 = __hmax2(v[6], v[7]);
            __half2 m03 = __hmax2(m01, m23),   m47 = __hmax2(m45, m67);
            __half2 m2  = __hmax2(m03, m47);
            float mx = fmaxf(__low2float(m2), __high2float(m2));
            mx = fmaxf(mx, __shfl_xor_sync(0xffffffffu, mx, 1));
            mx = fmaxf(mx, __shfl_xor_sync(0xffffffffu, mx, 2));
            __half2 noff = __float2half2_rn(-LOG2E64 * mx);
            __half2 e[8];
#pragma unroll
            for (int ni = 0; ni < 8; ni++)
                e[ni] = ex2_h2(__hfma2(v[ni], k2, noff));
            __half2 s01 = __hadd2(e[0], e[1]), s23 = __hadd2(e[2], e[3]);
            __half2 s45 = __hadd2(e[4], e[5]), s67 = __hadd2(e[6], e[7]);
            __half2 s03 = __hadd2(s01, s23),   s47 = __hadd2(s45, s67);
            __half2 st  = __hadd2(s03, s47);
            float s = __low2float(st) + __high2float(st);
            s += __shfl_xor_sync(0xffffffffu, s, 1);
            s += __shfl_xor_sync(0xffffffffu, s, 2);
            if ((lane & 3) == 0) { sMax[wn*BM + rw] = S_SCALE * mx; sSum[wn*BM + rw] = s; }
        }
    }
    __syncthreads();

    if (tid < BM) {
        float m = sMax[tid], s = sSum[tid];
        lse_combine(m, s, sMax[BM   + tid], sSum[BM   + tid]);
        lse_combine(m, s, sMax[2*BM + tid], sSum[2*BM + tid]);
        lse_combine(m, s, sMax[3*BM + tid], sSum[3*BM + tid]);
        int grow = m0 + tid;
        g_pmax[(size_t)grow * NT + ct] = m;
        g_psum[(size_t)grow * NT + ct] = s;
    }
}

// ---------------- final reductions ----------------
__global__ void reduce1_kernel() {
    int row = blockIdx.x, tid = threadIdx.x;   // 128 threads
    float mx = -1e30f, sm = 0.0f;
    for (int t = tid; t < NT; t += 128) {
        float m = g_pmax[(size_t)row * NT + t];
        float s = g_psum[(size_t)row * NT + t];
        lse_combine(mx, sm, m, s);
    }
#pragma unroll
    for (int o = 16; o > 0; o >>= 1) {
        float om = __shfl_xor_sync(0xffffffffu, mx, o);
        float os = __shfl_xor_sync(0xffffffffu, sm, o);
        lse_combine(mx, sm, om, os);
    }
    __shared__ float rm[4], rs[4];
    int lane = tid & 31, w = tid >> 5;
    if (lane == 0) { rm[w] = mx; rs[w] = sm; }
    __syncthreads();
    if (tid == 0) {
        float m = rm[0], s = rs[0];
        lse_combine(m, s, rm[1], rs[1]);
        lse_combine(m, s, rm[2], rs[2]);
        lse_combine(m, s, rm[3], rs[3]);
        // remove PADC padding terms (logit exactly 0), swap plain->adjusted label term
        float plain = g_lab_plain[row], adj = g_lab_adj[row];
        float s2 = s - (float)PADC * __expf(0.0f - m) - __expf(plain - m) + __expf(adj - m);
        float lse = m + __logf(s2);
        g_loss[row] = lse - adj;
    }
}

__global__ void reduce2_kernel(float* __restrict__ out) {
    int tid = threadIdx.x;    // 256 threads
    float s = 0.0f;
    for (int t = tid; t < NROWS; t += 256) s += g_loss[t];
    s = warpReduceSum(s);
    __shared__ float red[8];
    if ((tid & 31) == 0) red[tid >> 5] = s;
    __syncthreads();
    if (tid == 0) {
        float tot = 0.0f;
        for (int i = 0; i < 8; i++) tot += red[i];
        out[0] = tot / (float)NROWS;
    }
}

// ---------------- launch ----------------
extern "C" void kernel_launch(void* const* d_in, const int* in_sizes, int n_in,
                              void* d_out, int out_size) {
    const float* x      = (const float*)d_in[0];
    const int*   labels = (const int*)d_in[1];
    const float* w      = (const float*)d_in[2];
    float* out = (float*)d_out;

    cudaFuncSetAttribute(gemm_lse_kernel, cudaFuncAttributeMaxDynamicSharedMemorySize, SMEM_TOTAL);

    // order chosen so the GEMM sits at the ncu capture slot
    prep_x_kernel<<<NROWS, 128>>>(x);
    prep_w_kernel<<<CPAD, 128>>>(w);
    stats_kernel<<<1, 1024>>>();
    gemm_lse_kernel<<<dim3(8, NT), 256, SMEM_TOTAL>>>();
    label_kernel<<<NROWS, 128>>>(x, labels, w);
    reduce1_kernel<<<NROWS, 128>>>();
    reduce2_kernel<<<1, 256>>>(out);
}

// round 9
// speedup vs baseline: 2.2937x; 1.1411x over previous
#include <cuda_runtime.h>
#include <cuda_fp16.h>
#include <cstdint>
#include <math.h>

// Problem constants
#define NROWS 1024
#define DDIM  512
#define NCLS  70722
#define NT    277            // ceil(NCLS/256)
#define CPAD  (NT*256)       // 70912
#define PADC  (CPAD - NCLS)  // 190 zero padding classes (logit exactly 0)
#define M_MARGIN 0.4f
#define H_SCALE  0.333f
#define S_SCALE  64.0f
#define EPS_M    0.001f
#define PI_F     3.14159265358979f
#define LOG2E64  92.332482616893f   // 64 * log2(e)

// GEMM tiling (f16, HMMA m16n8k16, f16 accumulate)
#define BM 128
#define BN 256
#define BK 32                 // f16 elements per k-tile
#define PAD 8
#define ROWH (BK + PAD)       // 40 halfs per smem row
#define NKT (DDIM/BK)         // 16
#define NSTG 4

// dynamic smem layout (bytes)
#define A_ST   (BM*ROWH*2)            // 10240 per stage
#define B_ST   (BN*ROWH*2)            // 20480 per stage
#define SB_OFF (NSTG*A_ST)            // 40960
#define SMAX_OFF (SB_OFF + NSTG*B_ST) // 122880
#define SSUM_OFF (SMAX_OFF + 4*BM*4)  // +2048
#define SMEM_TOTAL (SSUM_OFF + 4*BM*4)// 126976

// ---------------- device scratch (static: no allocations) ----------------
__device__ __half g_A[NROWS*DDIM];               // normalized x, f16
__device__ __half g_W[(size_t)CPAD*DDIM];        // normalized weights, f16 (~72.6MB)
__device__ float g_xnorm[NROWS];
__device__ float g_gang[NROWS];
__device__ float g_gadd[NROWS];
__device__ float g_pmax[(size_t)NROWS*NT];
__device__ float g_psum[(size_t)NROWS*NT];
__device__ float g_lab_plain[NROWS];
__device__ float g_lab_adj[NROWS];
__device__ float g_loss[NROWS];

// ---------------- helpers ----------------
__device__ __forceinline__ float warpReduceSum(float v) {
#pragma unroll
    for (int o = 16; o > 0; o >>= 1) v += __shfl_xor_sync(0xffffffffu, v, o);
    return v;
}
__device__ __forceinline__ uint32_t smem_u32(const void* p) {
    return (uint32_t)__cvta_generic_to_shared(p);
}
__device__ __forceinline__ void cp16(uint32_t s, const void* g) {
    asm volatile("cp.async.cg.shared.global [%0], [%1], 16;\n" :: "r"(s), "l"(g));
}
__device__ __forceinline__ void lse_combine(float& m, float& s, float om, float os) {
    float nm = fmaxf(m, om);
    s = s * __expf(m - nm) + os * __expf(om - nm);
    m = nm;
}
__device__ __forceinline__ __half2 ex2_h2(__half2 a) {
    uint32_t au = *(uint32_t*)&a, ru;
    asm("ex2.approx.f16x2 %0, %1;" : "=r"(ru) : "r"(au));
    return *(__half2*)&ru;
}
__device__ __forceinline__ void ldmx4(uint32_t addr, uint32_t* r) {
    asm volatile("ldmatrix.sync.aligned.m8n8.x4.shared.b16 {%0,%1,%2,%3}, [%4];"
                 : "=r"(r[0]), "=r"(r[1]), "=r"(r[2]), "=r"(r[3]) : "r"(addr));
}

// ---------------- prep kernels ----------------
__global__ void prep_x_kernel(const float* __restrict__ x) {
    int row = blockIdx.x, tid = threadIdx.x;          // 128 threads
    const float4* xr = (const float4*)(x + (size_t)row * DDIM);
    float4 v = xr[tid];
    float s = v.x*v.x + v.y*v.y + v.z*v.z + v.w*v.w;
    __shared__ float red[4];
    s = warpReduceSum(s);
    if ((tid & 31) == 0) red[tid >> 5] = s;
    __syncthreads();
    float tot = red[0] + red[1] + red[2] + red[3];
    float nrm = sqrtf(tot);
    if (tid == 0) g_xnorm[row] = nrm;
    float inv = 1.0f / fmaxf(nrm, 1e-12f);
    __half2 h0 = __floats2half2_rn(v.x*inv, v.y*inv);
    __half2 h1 = __floats2half2_rn(v.z*inv, v.w*inv);
    uint2 pk; pk.x = *(unsigned*)&h0; pk.y = *(unsigned*)&h1;
    ((uint2*)g_A)[(size_t)row * (DDIM/4) + tid] = pk;
}

__global__ void prep_w_kernel(const float* __restrict__ w) {
    int row = blockIdx.x, tid = threadIdx.x;          // 128 threads, CPAD blocks
    uint2 pk;
    if (row < NCLS) {
        const float4* wr = (const float4*)(w + (size_t)row * DDIM);
        float4 v = wr[tid];
        float s = v.x*v.x + v.y*v.y + v.z*v.z + v.w*v.w;
        __shared__ float red[4];
        s = warpReduceSum(s);
        if ((tid & 31) == 0) red[tid >> 5] = s;
        __syncthreads();
        float tot = red[0] + red[1] + red[2] + red[3];
        float inv = 1.0f / fmaxf(sqrtf(tot), 1e-12f);
        __half2 h0 = __floats2half2_rn(v.x*inv, v.y*inv);
        __half2 h1 = __floats2half2_rn(v.z*inv, v.w*inv);
        pk.x = *(unsigned*)&h0; pk.y = *(unsigned*)&h1;
    } else {
        pk.x = 0u; pk.y = 0u;    // zero rows -> logit exactly 0, corrected in reduce1
    }
    ((uint2*)g_W)[(size_t)row * (DDIM/4) + tid] = pk;
}

__global__ void stats_kernel() {
    int tid = threadIdx.x;                            // 1024 threads
    float n = g_xnorm[tid];
    float s = fminf(fmaxf(fmaxf(n, 1e-8f), 0.001f), 100.0f);
    __shared__ float red[32];
    float t = warpReduceSum(s);
    if ((tid & 31) == 0) red[tid >> 5] = t;
    __syncthreads();
    if (tid < 32) { float v = red[tid]; v = warpReduceSum(v); if (tid == 0) red[0] = v; }
    __syncthreads();
    float mean = red[0] / (float)NROWS;
    float d = s - mean;
    __syncthreads();
    t = warpReduceSum(d * d);
    if ((tid & 31) == 0) red[tid >> 5] = t;
    __syncthreads();
    if (tid < 32) { float v = red[tid]; v = warpReduceSum(v); if (tid == 0) red[0] = v; }
    __syncthreads();
    float stdv = sqrtf(red[0] / (float)(NROWS - 1));   // ddof=1
    float ms = fminf(fmaxf(d / (stdv + EPS_M) * H_SCALE, -1.0f), 1.0f);
    g_gang[tid] = -M_MARGIN * ms;
    g_gadd[tid] = M_MARGIN + M_MARGIN * ms;
}

__global__ void label_kernel(const float* __restrict__ x,
                             const int* __restrict__ labels,
                             const float* __restrict__ w) {
    int i = blockIdx.x, tid = threadIdx.x;            // 128 threads
    int l = labels[i];
    l = max(0, min(l, NCLS - 1));                     // safety clamp
    const float4* xr = (const float4*)(x + (size_t)i * DDIM);
    const float4* wr = (const float4*)(w + (size_t)l * DDIM);
    float4 a = xr[tid], b = wr[tid];
    float dot = a.x*b.x + a.y*b.y + a.z*b.z + a.w*b.w;
    float wsq = b.x*b.x + b.y*b.y + b.z*b.z + b.w*b.w;
    __shared__ float rd[4], rw[4];
    dot = warpReduceSum(dot);
    wsq = warpReduceSum(wsq);
    if ((tid & 31) == 0) { rd[tid >> 5] = dot; rw[tid >> 5] = wsq; }
    __syncthreads();
    if (tid == 0) {
        float Dv = rd[0] + rd[1] + rd[2] + rd[3];
        float Wv = rw[0] + rw[1] + rw[2] + rw[3];
        float xn = fmaxf(g_xnorm[i], 1e-12f);
        float wn = fmaxf(sqrtf(Wv), 1e-12f);
        float c  = fminf(fmaxf(Dv / (xn * wn), -1.0f), 1.0f);
        float th = acosf(c);
        float plain = S_SCALE * cosf(fminf(fmaxf(th, EPS_M), PI_F - EPS_M));
        float thm = fminf(fmaxf(th + g_gang[i], EPS_M), PI_F - EPS_M);
        float adj = S_SCALE * (cosf(thm) - g_gadd[i]);
        g_lab_plain[i] = plain;
        g_lab_adj[i]   = adj;
    }
}

// ---------------- main fused f16 GEMM (f16 accumulate) + online LSE ----------------
// CTA tile 128x256, warp tile 64x64 (8 warps: 2m x 4n), 1 CTA/SM, double-buffered frags
__global__ void __launch_bounds__(256, 1) gemm_lse_kernel() {
    extern __shared__ __align__(16) char smem[];
    uint32_t sb = smem_u32(smem);
    float* sMax = (float*)(smem + SMAX_OFF);   // [4][BM]
    float* sSum = (float*)(smem + SSUM_OFF);   // [4][BM]

    int mt = blockIdx.x, ct = blockIdx.y;
    int tid = threadIdx.x;
    int lane = tid & 31, warp = tid >> 5;
    int wm = warp & 1;        // 0..1 -> m offset (64 each)
    int wn = warp >> 1;       // 0..3 -> n offset (64 each)

    const int m0 = mt * BM;
    const int n0 = ct * BN;

    // f16 accumulators: [mi=4][ni=8][2 halves-pairs]
    uint32_t acc[4][8][2];
#pragma unroll
    for (int i = 0; i < 4; i++)
#pragma unroll
        for (int j = 0; j < 8; j++) { acc[i][j][0] = 0u; acc[i][j][1] = 0u; }

    // loaders: each thread moves 2x16B for A and 4x16B for B per K-tile
    int ar = tid >> 2;            // 0..63
    int ac = (tid & 3) * 8;       // 0,8,16,24 (f16 elements)
    const __half* gA = g_A + (size_t)(m0 + ar) * DDIM + ac;
    const __half* gB = g_W + (size_t)(n0 + ar) * DDIM + ac;

#define LOAD_TILE(stg, kt) do {                                                   \
        int _k0 = (kt) * BK;                                                      \
        uint32_t _a = sb + (stg) * A_ST + (ar * ROWH + ac) * 2;                   \
        uint32_t _b = sb + SB_OFF + (stg) * B_ST + (ar * ROWH + ac) * 2;          \
        cp16(_a,                  gA + _k0);                                      \
        cp16(_a + 64*ROWH*2,      gA + (size_t)64*DDIM  + _k0);                   \
        cp16(_b,                  gB + _k0);                                      \
        cp16(_b + 64*ROWH*2,      gB + (size_t)64*DDIM  + _k0);                   \
        cp16(_b + 128*ROWH*2,     gB + (size_t)128*DDIM + _k0);                   \
        cp16(_b + 192*ROWH*2,     gB + (size_t)192*DDIM + _k0);                   \
        asm volatile("cp.async.commit_group;\n" ::);                              \
    } while (0)

    // fragment loaders for (stage, kk): A 4 x4-ldmatrix, B 4 x4-ldmatrix
    int arow0 = wm * 64 + (lane & 15);       // A base row (+16 per mi)
    int brow0 = wn * 64 + (lane & 15);       // B base row (+16 per nj-pair)
#define LD_FRAGS(stg, kk, fa, fb) do {                                            \
        int _kb = (kk) * 16 + (lane >> 4) * 8;                                    \
        uint32_t _ab = sb + (stg) * A_ST + _kb * 2;                               \
        uint32_t _bb = sb + SB_OFF + (stg) * B_ST + _kb * 2;                      \
        ldmx4(_ab + (arow0      ) * ROWH * 2, (fa)[0]);                           \
        ldmx4(_ab + (arow0 + 16 ) * ROWH * 2, (fa)[1]);                           \
        ldmx4(_ab + (arow0 + 32 ) * ROWH * 2, (fa)[2]);                           \
        ldmx4(_ab + (arow0 + 48 ) * ROWH * 2, (fa)[3]);                           \
        uint32_t _t[4];                                                           \
        ldmx4(_bb + (brow0      ) * ROWH * 2, _t);                                \
        (fb)[0][0]=_t[0]; (fb)[1][0]=_t[1]; (fb)[0][1]=_t[2]; (fb)[1][1]=_t[3];   \
        ldmx4(_bb + (brow0 + 16 ) * ROWH * 2, _t);                                \
        (fb)[2][0]=_t[0]; (fb)[3][0]=_t[1]; (fb)[2][1]=_t[2]; (fb)[3][1]=_t[3];   \
        ldmx4(_bb + (brow0 + 32 ) * ROWH * 2, _t);                                \
        (fb)[4][0]=_t[0]; (fb)[5][0]=_t[1]; (fb)[4][1]=_t[2]; (fb)[5][1]=_t[3];   \
        ldmx4(_bb + (brow0 + 48 ) * ROWH * 2, _t);                                \
        (fb)[6][0]=_t[0]; (fb)[7][0]=_t[1]; (fb)[6][1]=_t[2]; (fb)[7][1]=_t[3];   \
    } while (0)

#define MMA_SET(fa, fb) do {                                                      \
        _Pragma("unroll")                                                         \
        for (int mi = 0; mi < 4; mi++)                                            \
            _Pragma("unroll")                                                     \
            for (int ni = 0; ni < 8; ni++) {                                      \
                asm volatile(                                                     \
                    "mma.sync.aligned.m16n8k16.row.col.f16.f16.f16.f16 "          \
                    "{%0,%1}, {%2,%3,%4,%5}, {%6,%7}, {%0,%1};"                   \
                    : "+r"(acc[mi][ni][0]), "+r"(acc[mi][ni][1])                  \
                    : "r"((fa)[mi][0]), "r"((fa)[mi][1]),                         \
                      "r"((fa)[mi][2]), "r"((fa)[mi][3]),                         \
                      "r"((fb)[ni][0]), "r"((fb)[ni][1]));                        \
            }                                                                     \
    } while (0)

    // double-buffered fragments
    uint32_t fA0[4][4], fB0[8][2], fA1[4][4], fB1[8][2];

    LOAD_TILE(0, 0);
    LOAD_TILE(1, 1);
    LOAD_TILE(2, 2);
    asm volatile("cp.async.wait_group 2;\n" ::: "memory");
    __syncthreads();
    LD_FRAGS(0, 0, fA0, fB0);

    for (int kt = 0; kt < NKT; kt++) {
        int s = kt & 3;
        LD_FRAGS(s, 1, fA1, fB1);          // kk=1 frags issue under kk=0 MMAs
        MMA_SET(fA0, fB0);
        if (kt + 3 < NKT) LOAD_TILE((kt + 3) & 3, kt + 3);
        else asm volatile("cp.async.commit_group;\n" ::);
        MMA_SET(fA1, fB1);
        asm volatile("cp.async.wait_group 2;\n" ::: "memory");
        __syncthreads();
        if (kt + 1 < NKT) LD_FRAGS((kt + 1) & 3, 0, fA0, fB0);
    }
#undef LOAD_TILE
#undef LD_FRAGS
#undef MMA_SET

    // ---- epilogue: packed f16x2 clamp -> max -> ex2.f16x2 -> sum ----
    const __half2 h2hi = __float2half2_rn(1.0f);
    const __half2 h2lo = __float2half2_rn(-1.0f);
    const __half2 k2   = __float2half2_rn(LOG2E64);
#pragma unroll
    for (int mi = 0; mi < 4; mi++) {
#pragma unroll
        for (int hf = 0; hf < 2; hf++) {            // hf selects row group (+8)
            int rw = wm*64 + mi*16 + hf*8 + (lane >> 2);     // row within CTA
            __half2 v[8];
#pragma unroll
            for (int ni = 0; ni < 8; ni++) {
                __half2 c2 = *(__half2*)&acc[mi][ni][hf];
                v[ni] = __hmin2(__hmax2(c2, h2lo), h2hi);
            }
            __half2 m01 = __hmax2(v[0], v[1]), m23 = __hmax2(v[2], v[3]);
            __half2 m45 = __hmax2(v[4], v[5]), m67 = __hmax2(v[6], v[7]);
            __half2 m03 = __hmax2(m01, m23),   m47 = __hmax2(m45, m67);
            __half2 m2  = __hmax2(m03, m47);
            float mx = fmaxf(__low2float(m2), __high2float(m2));
            mx = fmaxf(mx, __shfl_xor_sync(0xffffffffu, mx, 1));
            mx = fmaxf(mx, __shfl_xor_sync(0xffffffffu, mx, 2));
            __half2 noff = __float2half2_rn(-LOG2E64 * mx);
            __half2 e[8];
#pragma unroll
            for (int ni = 0; ni < 8; ni++)
                e[ni] = ex2_h2(__hfma2(v[ni], k2, noff));
            __half2 s01 = __hadd2(e[0], e[1]), s23 = __hadd2(e[2], e[3]);
            __half2 s45 = __hadd2(e[4], e[5]), s67 = __hadd2(e[6], e[7]);
            __half2 s03 = __hadd2(s01, s23),   s47 = __hadd2(s45, s67);
            __half2 st  = __hadd2(s03, s47);
            float s = __low2float(st) + __high2float(st);
            s += __shfl_xor_sync(0xffffffffu, s, 1);
            s += __shfl_xor_sync(0xffffffffu, s, 2);
            if ((lane & 3) == 0) { sMax[wn*BM + rw] = S_SCALE * mx; sSum[wn*BM + rw] = s; }
        }
    }
    __syncthreads();

    if (tid < BM) {
        float m = sMax[tid], s = sSum[tid];
        lse_combine(m, s, sMax[BM   + tid], sSum[BM   + tid]);
        lse_combine(m, s, sMax[2*BM + tid], sSum[2*BM + tid]);
        lse_combine(m, s, sMax[3*BM + tid], sSum[3*BM + tid]);
        int grow = m0 + tid;
        g_pmax[(size_t)grow * NT + ct] = m;
        g_psum[(size_t)grow * NT + ct] = s;
    }
}

// ---------------- final reductions ----------------
__global__ void reduce1_kernel() {
    int row = blockIdx.x, tid = threadIdx.x;   // 128 threads
    float mx = -1e30f, sm = 0.0f;
    for (int t = tid; t < NT; t += 128) {
        float m = g_pmax[(size_t)row * NT + t];
        float s = g_psum[(size_t)row * NT + t];
        lse_combine(mx, sm, m, s);
    }
#pragma unroll
    for (int o = 16; o > 0; o >>= 1) {
        float om = __shfl_xor_sync(0xffffffffu, mx, o);
        float os = __shfl_xor_sync(0xffffffffu, sm, o);
        lse_combine(mx, sm, om, os);
    }
    __shared__ float rm[4], rs[4];
    int lane = tid & 31, w = tid >> 5;
    if (lane == 0) { rm[w] = mx; rs[w] = sm; }
    __syncthreads();
    if (tid == 0) {
        float m = rm[0], s = rs[0];
        lse_combine(m, s, rm[1], rs[1]);
        lse_combine(m, s, rm[2], rs[2]);
        lse_combine(m, s, rm[3], rs[3]);
        // remove PADC padding terms (logit exactly 0), swap plain->adjusted label term
        float plain = g_lab_plain[row], adj = g_lab_adj[row];
        float s2 = s - (float)PADC * __expf(0.0f - m) - __expf(plain - m) + __expf(adj - m);
        float lse = m + __logf(s2);
        g_loss[row] = lse - adj;
    }
}

__global__ void reduce2_kernel(float* __restrict__ out) {
    int tid = threadIdx.x;    // 256 threads
    float s = 0.0f;
    for (int t = tid; t < NROWS; t += 256) s += g_loss[t];
    s = warpReduceSum(s);
    __shared__ float red[8];
    if ((tid & 31) == 0) red[tid >> 5] = s;
    __syncthreads();
    if (tid == 0) {
        float tot = 0.0f;
        for (int i = 0; i < 8; i++) tot += red[i];
        out[0] = tot / (float)NROWS;
    }
}

// ---------------- launch ----------------
extern "C" void kernel_launch(void* const* d_in, const int* in_sizes, int n_in,
                              void* d_out, int out_size) {
    const float* x      = (const float*)d_in[0];
    const int*   labels = (const int*)d_in[1];
    const float* w      = (const float*)d_in[2];
    float* out = (float*)d_out;

    cudaFuncSetAttribute(gemm_lse_kernel, cudaFuncAttributeMaxDynamicSharedMemorySize, SMEM_TOTAL);

    // order chosen so the GEMM sits at the ncu capture slot
    prep_x_kernel<<<NROWS, 128>>>(x);
    prep_w_kernel<<<CPAD, 128>>>(w);
    stats_kernel<<<1, 1024>>>();
    gemm_lse_kernel<<<dim3(8, NT), 256, SMEM_TOTAL>>>();
    label_kernel<<<NROWS, 128>>>(x, labels, w);
    reduce1_kernel<<<NROWS, 128>>>();
    reduce2_kernel<<<1, 256>>>(out);
}